// round 1
// baseline (speedup 1.0000x reference)
#include <cuda_runtime.h>

#define Nn 30000
#define Ee 480000

// ---------------- scratch (static device allocations; no cudaMalloc) ----------------
__device__ __align__(16) float g_geom[Ee * 4];   // r, ux, uy, uz
__device__ float g_h[Ee * 32];
__device__ float g_m0[Ee * 32];
__device__ float g_logit[Ee * 4];
__device__ float g_q[Nn * 32];
__device__ float g_f0[Nn * 32];
__device__ float g_f1[Nn * 96];
__device__ float g_f2[Nn * 160];
__device__ float g_agg[Nn * 288];   // [n][c][9]: 0=agg0, 1..3=agg1, 4..8=agg2
__device__ int g_deg[Nn];
__device__ int g_off[Nn + 1];
__device__ int g_cur[Nn];
__device__ int g_eid[Ee];

// ---------------- CSR build ----------------
__global__ void zero_deg_kernel() {
    int i = blockIdx.x * blockDim.x + threadIdx.x;
    if (i < Nn) g_deg[i] = 0;
}

__global__ void geom_hist_kernel(const float* __restrict__ pos,
                                 const int* __restrict__ esrc,
                                 const int* __restrict__ edst) {
    int e = blockIdx.x * blockDim.x + threadIdx.x;
    if (e >= Ee) return;
    int s = esrc[e], d = edst[e];
    float rx = pos[d * 3 + 0] - pos[s * 3 + 0];
    float ry = pos[d * 3 + 1] - pos[s * 3 + 1];
    float rz = pos[d * 3 + 2] - pos[s * 3 + 2];
    float r = sqrtf(rx * rx + ry * ry + rz * rz + 1e-8f);
    float inv = 1.0f / r;
    ((float4*)g_geom)[e] = make_float4(r, rx * inv, ry * inv, rz * inv);
    atomicAdd(&g_deg[d], 1);
}

__global__ void scan_kernel() {
    __shared__ int sp[1024];
    const int CH = 30;  // 1024*30 >= 30000
    int t = threadIdx.x;
    int loc[CH];
    int base = t * CH;
    int s = 0;
#pragma unroll
    for (int i = 0; i < CH; i++) {
        int idx = base + i;
        int v = (idx < Nn) ? g_deg[idx] : 0;
        loc[i] = v;
        s += v;
    }
    sp[t] = s;
    __syncthreads();
    for (int off = 1; off < 1024; off <<= 1) {
        int v = (t >= off) ? sp[t - off] : 0;
        __syncthreads();
        sp[t] += v;
        __syncthreads();
    }
    int run = (t == 0) ? 0 : sp[t - 1];
#pragma unroll
    for (int i = 0; i < CH; i++) {
        int idx = base + i;
        if (idx < Nn) { g_off[idx] = run; run += loc[i]; }
    }
    if (t == 1023) g_off[Nn] = sp[1023];
}

__global__ void cursor_kernel() {
    int i = blockIdx.x * blockDim.x + threadIdx.x;
    if (i < Nn) g_cur[i] = g_off[i];
}

__global__ void scatter_kernel(const int* __restrict__ edst) {
    int e = blockIdx.x * blockDim.x + threadIdx.x;
    if (e >= Ee) return;
    int d = edst[e];
    int p = atomicAdd(&g_cur[d], 1);
    g_eid[p] = e;
}

__global__ void copy_f0_kernel(const float* __restrict__ src) {
    int i = blockIdx.x * blockDim.x + threadIdx.x;
    if (i < Nn * 32) g_f0[i] = src[i];
}

// ---------------- per-layer kernels ----------------
// q[n][j] = sum_c f0[n][c] * Wq[c][j]   (warp per node)
__global__ __launch_bounds__(256) void q_kernel(const float* __restrict__ Wq) {
    __shared__ float sW[1024];
    __shared__ float sf[8][32];
    int tid = threadIdx.x;
    for (int i = tid; i < 1024; i += 256) sW[i] = Wq[i];
    __syncthreads();
    int warp = tid >> 5, lane = tid & 31;
    int n = blockIdx.x * 8 + warp;
    if (n >= Nn) return;
    sf[warp][lane] = g_f0[n * 32 + lane];
    __syncwarp();
    float acc = 0.f;
#pragma unroll
    for (int c = 0; c < 32; c++) acc += sf[warp][c] * sW[c * 32 + lane];
    g_q[n * 32 + lane] = acc;
}

// Thread-per-edge: radial MLP hidden h (stored), message m0 (stored),
// k = m0@Wk, logits = q[dst].k per head (stored).
template <bool FIRST>
__global__ __launch_bounds__(128) void edge_kernel(
    const float* __restrict__ edge_feat, const int* __restrict__ esrc,
    const int* __restrict__ edst, const float* __restrict__ Wr1,
    const float* __restrict__ br1, const float* __restrict__ Wr2,
    const float* __restrict__ Wk) {
    __shared__ __align__(16) float sWr1[33 * 32];
    __shared__ float sbr1[32];
    __shared__ __align__(16) float sWr2T[96 * 32];  // [pc][j], pc = p*32+c for p=0..2
    __shared__ __align__(16) float sWk[32 * 32];
    int tid = threadIdx.x;
    for (int i = tid; i < 33 * 32; i += 128) sWr1[i] = Wr1[i];
    if (tid < 32) sbr1[tid] = br1[tid];
    const int PC = FIRST ? 32 : 96;
    for (int i = tid; i < PC * 32; i += 128) {
        int pc = i >> 5, j = i & 31;
        sWr2T[i] = Wr2[j * 224 + pc];
    }
    for (int i = tid; i < 1024; i += 128) sWk[i] = Wk[i];
    __syncthreads();
    int e = blockIdx.x * 128 + tid;
    if (e >= Ee) return;
    int src = esrc[e], dst = edst[e];
    float4 gm = ((const float4*)g_geom)[e];
    float r = gm.x, ux = gm.y, uy = gm.z, uz = gm.w;

    float h[32];
#pragma unroll
    for (int j = 0; j < 32; j++) h[j] = sbr1[j] + r * sWr1[j];
    const float4* ef4 = (const float4*)(edge_feat + (size_t)e * 32);
#pragma unroll
    for (int i4 = 0; i4 < 8; i4++) {
        float4 v = ef4[i4];
        float vv[4] = {v.x, v.y, v.z, v.w};
#pragma unroll
        for (int q = 0; q < 4; q++) {
            const float4* wr = (const float4*)&sWr1[(i4 * 4 + q + 1) * 32];
#pragma unroll
            for (int j4 = 0; j4 < 8; j4++) {
                float4 a = wr[j4];
                h[j4 * 4 + 0] += vv[q] * a.x;
                h[j4 * 4 + 1] += vv[q] * a.y;
                h[j4 * 4 + 2] += vv[q] * a.z;
                h[j4 * 4 + 3] += vv[q] * a.w;
            }
        }
    }
#pragma unroll
    for (int j = 0; j < 32; j++) h[j] = fmaxf(h[j], 0.f);
    {
        float4* hp = (float4*)&g_h[(size_t)e * 32];
#pragma unroll
        for (int j4 = 0; j4 < 8; j4++)
            hp[j4] = make_float4(h[j4 * 4], h[j4 * 4 + 1], h[j4 * 4 + 2], h[j4 * 4 + 3]);
    }

    float s0 = ux * uy, s1 = uy * uz, s2 = 3.f * uz * uz - 1.f;
    float s3 = ux * uz, s4 = ux * ux - uy * uy;
    float k[32];
#pragma unroll
    for (int j = 0; j < 32; j++) k[j] = 0.f;
    const float* f0row = &g_f0[(size_t)src * 32];
    const float* f1row = &g_f1[(size_t)src * 96];
    const float* f2row = &g_f2[(size_t)src * 160];
    float m0st[4];
    float4* m0p = (float4*)&g_m0[(size_t)e * 32];
    for (int c = 0; c < 32; c++) {
        float w0 = 0.f;
        const float4* p0 = (const float4*)&sWr2T[c * 32];
#pragma unroll
        for (int j4 = 0; j4 < 8; j4++) {
            float4 a = p0[j4];
            w0 += a.x * h[j4 * 4] + a.y * h[j4 * 4 + 1] + a.z * h[j4 * 4 + 2] + a.w * h[j4 * 4 + 3];
        }
        float m0c = w0 * f0row[c];
        if (!FIRST) {
            float w1 = 0.f, w2 = 0.f;
            const float4* p1 = (const float4*)&sWr2T[(32 + c) * 32];
            const float4* p2 = (const float4*)&sWr2T[(64 + c) * 32];
#pragma unroll
            for (int j4 = 0; j4 < 8; j4++) {
                float4 a = p1[j4];
                w1 += a.x * h[j4 * 4] + a.y * h[j4 * 4 + 1] + a.z * h[j4 * 4 + 2] + a.w * h[j4 * 4 + 3];
            }
#pragma unroll
            for (int j4 = 0; j4 < 8; j4++) {
                float4 a = p2[j4];
                w2 += a.x * h[j4 * 4] + a.y * h[j4 * 4 + 1] + a.z * h[j4 * 4 + 2] + a.w * h[j4 * 4 + 3];
            }
            float d1 = f1row[c * 3] * ux + f1row[c * 3 + 1] * uy + f1row[c * 3 + 2] * uz;
            float d2 = f2row[c * 5] * s0 + f2row[c * 5 + 1] * s1 + f2row[c * 5 + 2] * s2 +
                       f2row[c * 5 + 3] * s3 + f2row[c * 5 + 4] * s4;
            m0c += w1 * d1 + w2 * d2;
        }
        m0st[c & 3] = m0c;
        if ((c & 3) == 3)
            m0p[c >> 2] = make_float4(m0st[0], m0st[1], m0st[2], m0st[3]);
        const float4* kp = (const float4*)&sWk[c * 32];
#pragma unroll
        for (int j4 = 0; j4 < 8; j4++) {
            float4 a = kp[j4];
            k[j4 * 4 + 0] += m0c * a.x;
            k[j4 * 4 + 1] += m0c * a.y;
            k[j4 * 4 + 2] += m0c * a.z;
            k[j4 * 4 + 3] += m0c * a.w;
        }
    }
    const float* qrow = &g_q[(size_t)dst * 32];
#pragma unroll
    for (int hh = 0; hh < 4; hh++) {
        float lg = 0.f;
#pragma unroll
        for (int d = 0; d < 8; d++) lg += qrow[hh * 8 + d] * k[hh * 8 + d];
        g_logit[(size_t)e * 4 + hh] = lg * 0.35355339059327373f;  // 1/sqrt(8)
    }
}

// Warp-per-node: fused segment softmax (max, den) + weighted aggregation into
// register accumulators. Recomputes w3..w6 from stored h via shfl + float4 smem.
template <bool FIRST>
__global__ __launch_bounds__(256) void agg_kernel(const int* __restrict__ esrc,
                                                  const float* __restrict__ Wr2) {
    __shared__ __align__(16) float4 sW4[32 * 32];  // [j][lane] -> (w3,w4,w5,w6) cols
    int tid = threadIdx.x;
    for (int i = tid; i < 1024; i += 256) {
        int j = i >> 5, c = i & 31;
        const float* row = Wr2 + j * 224;
        if (FIRST)
            sW4[i] = make_float4(row[96 + c], row[160 + c], 0.f, 0.f);
        else
            sW4[i] = make_float4(row[96 + c], row[128 + c], row[160 + c], row[192 + c]);
    }
    __syncthreads();
    int lane = tid & 31;
    int n = blockIdx.x * 8 + (tid >> 5);
    if (n >= Nn) return;
    int beg = g_off[n], end = g_off[n + 1];
    int myh = lane >> 3;

    float mx = -3.0e38f;
    for (int i = beg; i < end; i++)
        mx = fmaxf(mx, g_logit[(size_t)g_eid[i] * 4 + myh]);
    float den = 0.f;
    for (int i = beg; i < end; i++)
        den += __expf(g_logit[(size_t)g_eid[i] * 4 + myh] - mx);
    float dinv = 1.f / (den + 1e-8f);

    float a0 = 0.f, a10 = 0.f, a11 = 0.f, a12 = 0.f;
    float a20 = 0.f, a21 = 0.f, a22 = 0.f, a23 = 0.f, a24 = 0.f;
    for (int i = beg; i < end; i++) {
        int eid = g_eid[i];
        float alpha = __expf(g_logit[(size_t)eid * 4 + myh] - mx) * dinv;
        float hreg = g_h[(size_t)eid * 32 + lane];
        float m0c = g_m0[(size_t)eid * 32 + lane];
        int src = esrc[eid];
        float4 gm = ((const float4*)g_geom)[eid];
        float ux = gm.y, uy = gm.z, uz = gm.w;
        float y0 = ux * uy, y1 = uy * uz, y2 = 3.f * uz * uz - 1.f;
        float y3 = ux * uz, y4 = ux * ux - uy * uy;
        float w3 = 0.f, w4 = 0.f, w5 = 0.f, w6 = 0.f;
#pragma unroll
        for (int j = 0; j < 32; j++) {
            float hj = __shfl_sync(0xffffffffu, hreg, j);
            float4 a = sW4[j * 32 + lane];
            if (FIRST) {
                w3 += hj * a.x; w5 += hj * a.y;
            } else {
                w3 += hj * a.x; w4 += hj * a.y; w5 += hj * a.z; w6 += hj * a.w;
            }
        }
        float f0s = g_f0[(size_t)src * 32 + lane];
        a0 += alpha * m0c;
        float wf3 = w3 * f0s * alpha, wf5 = w5 * f0s * alpha;
        if (FIRST) {
            a10 += wf3 * ux; a11 += wf3 * uy; a12 += wf3 * uz;
            a20 += wf5 * y0; a21 += wf5 * y1; a22 += wf5 * y2;
            a23 += wf5 * y3; a24 += wf5 * y4;
        } else {
            const float* f1s = &g_f1[(size_t)src * 96 + lane * 3];
            const float* f2s = &g_f2[(size_t)src * 160 + lane * 5];
            float aw4 = alpha * w4, aw6 = alpha * w6;
            a10 += wf3 * ux + aw4 * f1s[0];
            a11 += wf3 * uy + aw4 * f1s[1];
            a12 += wf3 * uz + aw4 * f1s[2];
            a20 += wf5 * y0 + aw6 * f2s[0];
            a21 += wf5 * y1 + aw6 * f2s[1];
            a22 += wf5 * y2 + aw6 * f2s[2];
            a23 += wf5 * y3 + aw6 * f2s[3];
            a24 += wf5 * y4 + aw6 * f2s[4];
        }
    }
    float* ag = &g_agg[(size_t)n * 288 + lane * 9];
    ag[0] = a0;
    ag[1] = a10; ag[2] = a11; ag[3] = a12;
    ag[4] = a20; ag[5] = a21; ag[6] = a22; ag[7] = a23; ag[8] = a24;
}

// Warp-per-node: f0' = agg0@Ws0 + f0@Wskip; f1'[o][m]=sum_c agg1[c][m]*Ws1[c][o]; f2' similar.
__global__ __launch_bounds__(256) void update_kernel(const float* __restrict__ Ws0,
                                                     const float* __restrict__ Ws1,
                                                     const float* __restrict__ Ws2,
                                                     const float* __restrict__ Wsk) {
    __shared__ __align__(16) float s0[1024], s1[1024], s2[1024], sk[1024];
    __shared__ float sf0[8][32];
    __shared__ float sag[8][288];
    int tid = threadIdx.x;
    for (int i = tid; i < 1024; i += 256) {
        s0[i] = Ws0[i]; s1[i] = Ws1[i]; s2[i] = Ws2[i]; sk[i] = Wsk[i];
    }
    __syncthreads();
    int warp = tid >> 5, lane = tid & 31;
    int n = blockIdx.x * 8 + warp;
    if (n >= Nn) return;
    sf0[warp][lane] = g_f0[(size_t)n * 32 + lane];
#pragma unroll
    for (int s = 0; s < 9; s++)
        sag[warp][lane * 9 + s] = g_agg[(size_t)n * 288 + lane * 9 + s];
    __syncwarp();
    float o0 = 0.f, o10 = 0.f, o11 = 0.f, o12 = 0.f;
    float o20 = 0.f, o21 = 0.f, o22 = 0.f, o23 = 0.f, o24 = 0.f;
#pragma unroll 4
    for (int c = 0; c < 32; c++) {
        const float* ac = &sag[warp][c * 9];
        o0 += ac[0] * s0[c * 32 + lane] + sf0[warp][c] * sk[c * 32 + lane];
        float w1 = s1[c * 32 + lane];
        o10 += ac[1] * w1; o11 += ac[2] * w1; o12 += ac[3] * w1;
        float w2 = s2[c * 32 + lane];
        o20 += ac[4] * w2; o21 += ac[5] * w2; o22 += ac[6] * w2;
        o23 += ac[7] * w2; o24 += ac[8] * w2;
    }
    g_f0[(size_t)n * 32 + lane] = o0;
    float* f1w = &g_f1[(size_t)n * 96 + lane * 3];
    f1w[0] = o10; f1w[1] = o11; f1w[2] = o12;
    float* f2w = &g_f2[(size_t)n * 160 + lane * 5];
    f2w[0] = o20; f2w[1] = o21; f2w[2] = o22; f2w[3] = o23; f2w[4] = o24;
}

// hs0 = f0@Wout -> out[0 : N*32);  cs = hs0@Wc -> out[N*32 : N*32+N*15)
__global__ __launch_bounds__(128) void out_kernel(const float* __restrict__ Wout,
                                                  const float* __restrict__ Wc,
                                                  float* __restrict__ out) {
    __shared__ __align__(16) float sWo[1024];
    __shared__ float sWc[480];
    int tid = threadIdx.x;
    for (int i = tid; i < 1024; i += 128) sWo[i] = Wout[i];
    for (int i = tid; i < 480; i += 128) sWc[i] = Wc[i];
    __syncthreads();
    int n = blockIdx.x * 128 + tid;
    if (n >= Nn) return;
    float hs[32];
#pragma unroll
    for (int j = 0; j < 32; j++) hs[j] = 0.f;
    const float* f0r = &g_f0[(size_t)n * 32];
#pragma unroll 4
    for (int c = 0; c < 32; c++) {
        float v = f0r[c];
        const float4* wr = (const float4*)&sWo[c * 32];
#pragma unroll
        for (int j4 = 0; j4 < 8; j4++) {
            float4 a = wr[j4];
            hs[j4 * 4 + 0] += v * a.x;
            hs[j4 * 4 + 1] += v * a.y;
            hs[j4 * 4 + 2] += v * a.z;
            hs[j4 * 4 + 3] += v * a.w;
        }
    }
    float4* op = (float4*)&out[(size_t)n * 32];
#pragma unroll
    for (int j4 = 0; j4 < 8; j4++)
        op[j4] = make_float4(hs[j4 * 4], hs[j4 * 4 + 1], hs[j4 * 4 + 2], hs[j4 * 4 + 3]);
    float* cp = &out[(size_t)Nn * 32 + (size_t)n * 15];
#pragma unroll
    for (int t = 0; t < 15; t++) {
        float acc = 0.f;
#pragma unroll
        for (int j = 0; j < 32; j++) acc += hs[j] * sWc[j * 15 + t];
        cp[t] = acc;
    }
}

// ---------------- launch ----------------
extern "C" void kernel_launch(void* const* d_in, const int* in_sizes, int n_in,
                              void* d_out, int out_size) {
    const float* pos       = (const float*)d_in[0];
    const float* node_l0   = (const float*)d_in[1];
    const float* edge_feat = (const float*)d_in[2];
    const int*   esrc      = (const int*)d_in[3];
    const int*   edst      = (const int*)d_in[4];
    const float* Wr1       = (const float*)d_in[5];
    const float* br1       = (const float*)d_in[6];
    const float* Wr2       = (const float*)d_in[7];
    const float* Wq        = (const float*)d_in[8];
    const float* Wk        = (const float*)d_in[9];
    const float* Ws0       = (const float*)d_in[10];
    const float* Ws1       = (const float*)d_in[11];
    const float* Ws2       = (const float*)d_in[12];
    const float* Wsk       = (const float*)d_in[13];
    const float* Wout      = (const float*)d_in[14];
    const float* Wc        = (const float*)d_in[15];
    float* out = (float*)d_out;

    zero_deg_kernel<<<(Nn + 255) / 256, 256>>>();
    geom_hist_kernel<<<(Ee + 255) / 256, 256>>>(pos, esrc, edst);
    scan_kernel<<<1, 1024>>>();
    cursor_kernel<<<(Nn + 255) / 256, 256>>>();
    scatter_kernel<<<(Ee + 255) / 256, 256>>>(edst);
    copy_f0_kernel<<<(Nn * 32 + 255) / 256, 256>>>(node_l0);

    const int NODE_BLKS = (Nn + 7) / 8;
    // layer 0 (f1=f2=0 specialization)
    q_kernel<<<NODE_BLKS, 256>>>(Wq);
    edge_kernel<true><<<(Ee + 127) / 128, 128>>>(edge_feat, esrc, edst, Wr1, br1, Wr2, Wk);
    agg_kernel<true><<<NODE_BLKS, 256>>>(esrc, Wr2);
    update_kernel<<<NODE_BLKS, 256>>>(Ws0, Ws1, Ws2, Wsk);
    // layer 1
    q_kernel<<<NODE_BLKS, 256>>>(Wq + 1024);
    edge_kernel<false><<<(Ee + 127) / 128, 128>>>(edge_feat, esrc, edst, Wr1 + 1056,
                                                  br1 + 32, Wr2 + 7168, Wk + 1024);
    agg_kernel<false><<<NODE_BLKS, 256>>>(esrc, Wr2 + 7168);
    update_kernel<<<NODE_BLKS, 256>>>(Ws0 + 1024, Ws1 + 1024, Ws2 + 1024, Wsk + 1024);

    out_kernel<<<(Nn + 127) / 128, 128>>>(Wout, Wc, out);
}

// round 3
// speedup vs baseline: 1.5485x; 1.5485x over previous
#include <cuda_runtime.h>

#define Nn 30000
#define Ee 480000
#define FULLMASK 0xffffffffu

// ---------------- scratch (static device allocations; no cudaMalloc) ----------------
__device__ __align__(16) float g_geom[Ee * 4];   // r, ux, uy, uz
__device__ __align__(16) float g_m0[Ee * 32];
__device__ __align__(16) float g_w[Ee * 128];    // [E][32] float4 (w3,w4,w5,w6); layer0: [E][32] float2 (w3,w5)
__device__ __align__(16) float g_logit[Ee * 4];
__device__ float g_q[Nn * 32];
__device__ float g_f0[Nn * 32];
__device__ float g_f1[Nn * 96];
__device__ float g_f2[Nn * 160];
__device__ float g_agg[Nn * 288];   // [n][c][9]: 0=agg0, 1..3=agg1, 4..8=agg2
__device__ int g_deg[Nn];
__device__ int g_off[Nn + 1];
__device__ int g_cur[Nn];
__device__ int g_eid[Ee];

// ---------------- CSR build ----------------
__global__ void zero_deg_kernel() {
    int i = blockIdx.x * blockDim.x + threadIdx.x;
    if (i < Nn) g_deg[i] = 0;
}

__global__ void geom_hist_kernel(const float* __restrict__ pos,
                                 const int* __restrict__ esrc,
                                 const int* __restrict__ edst) {
    int e = blockIdx.x * blockDim.x + threadIdx.x;
    if (e >= Ee) return;
    int s = esrc[e], d = edst[e];
    float rx = pos[d * 3 + 0] - pos[s * 3 + 0];
    float ry = pos[d * 3 + 1] - pos[s * 3 + 1];
    float rz = pos[d * 3 + 2] - pos[s * 3 + 2];
    float r = sqrtf(rx * rx + ry * ry + rz * rz + 1e-8f);
    float inv = 1.0f / r;
    ((float4*)g_geom)[e] = make_float4(r, rx * inv, ry * inv, rz * inv);
    atomicAdd(&g_deg[d], 1);
}

__global__ void scan_kernel() {
    __shared__ int sp[1024];
    const int CH = 30;  // 1024*30 >= 30000
    int t = threadIdx.x;
    int loc[CH];
    int base = t * CH;
    int s = 0;
#pragma unroll
    for (int i = 0; i < CH; i++) {
        int idx = base + i;
        int v = (idx < Nn) ? g_deg[idx] : 0;
        loc[i] = v;
        s += v;
    }
    sp[t] = s;
    __syncthreads();
    for (int off = 1; off < 1024; off <<= 1) {
        int v = (t >= off) ? sp[t - off] : 0;
        __syncthreads();
        sp[t] += v;
        __syncthreads();
    }
    int run = (t == 0) ? 0 : sp[t - 1];
#pragma unroll
    for (int i = 0; i < CH; i++) {
        int idx = base + i;
        if (idx < Nn) { g_off[idx] = run; run += loc[i]; }
    }
    if (t == 1023) g_off[Nn] = sp[1023];
}

__global__ void cursor_kernel() {
    int i = blockIdx.x * blockDim.x + threadIdx.x;
    if (i < Nn) g_cur[i] = g_off[i];
}

__global__ void scatter_kernel(const int* __restrict__ edst) {
    int e = blockIdx.x * blockDim.x + threadIdx.x;
    if (e >= Ee) return;
    int d = edst[e];
    int p = atomicAdd(&g_cur[d], 1);
    g_eid[p] = e;
}

__global__ void copy_f0_kernel(const float* __restrict__ src) {
    int i = blockIdx.x * blockDim.x + threadIdx.x;
    if (i < Nn * 32) g_f0[i] = src[i];
}

// ---------------- per-layer kernels ----------------
// q[n][j] = sum_c f0[n][c] * Wq[c][j]   (warp per node, coalesced)
__global__ __launch_bounds__(256) void q_kernel(const float* __restrict__ Wq) {
    __shared__ float sW[1024];
    int tid = threadIdx.x;
    for (int i = tid; i < 1024; i += 256) sW[i] = Wq[i];
    __syncthreads();
    int warp = tid >> 5, lane = tid & 31;
    int n = blockIdx.x * 8 + warp;
    if (n >= Nn) return;
    float f = g_f0[(size_t)n * 32 + lane];
    float acc = 0.f;
#pragma unroll
    for (int c = 0; c < 32; c++) {
        float fc = __shfl_sync(FULLMASK, f, c);
        acc = fmaf(fc, sW[c * 32 + lane], acc);
    }
    g_q[(size_t)n * 32 + lane] = acc;
}

// Warp-per-edge: radial MLP -> w's, m0 (stored), w3..6 (stored),
// k = m0@Wk, logits = q[dst].k per head (stored). lane = channel.
template <bool FIRST>
__global__ __launch_bounds__(256) void edge_kernel(
    const float* __restrict__ edge_feat, const int* __restrict__ esrc,
    const int* __restrict__ edst, const float* __restrict__ Wr1,
    const float* __restrict__ br1, const float* __restrict__ Wr2,
    const float* __restrict__ Wk) {
    __shared__ __align__(16) float sWr1[33 * 32];
    __shared__ float sbr1[32];
    __shared__ __align__(16) float4 sW2a[1024];  // [j][c] -> (p0,p1,p2,p3) | layer0 (p0,p3,p5,-)
    __shared__ __align__(16) float4 sW2b[1024];  // [j][c] -> (p4,p5,p6,-)   | layer0 unused
    __shared__ __align__(16) float sWk[1024];
    int tid = threadIdx.x;
    for (int i = tid; i < 33 * 32; i += 256) sWr1[i] = Wr1[i];
    if (tid < 32) sbr1[tid] = br1[tid];
    for (int i = tid; i < 1024; i += 256) {
        int j = i >> 5, c = i & 31;
        const float* row = Wr2 + j * 224;
        if (FIRST) {
            sW2a[i] = make_float4(row[c], row[96 + c], row[160 + c], 0.f);
        } else {
            sW2a[i] = make_float4(row[c], row[32 + c], row[64 + c], row[96 + c]);
            sW2b[i] = make_float4(row[128 + c], row[160 + c], row[192 + c], 0.f);
        }
        sWk[i] = Wk[i];
    }
    __syncthreads();
    int lane = tid & 31;
    int e = blockIdx.x * 8 + (tid >> 5);
    if (e >= Ee) return;
    int src = esrc[e], dst = edst[e];
    float4 gm = ((const float4*)g_geom)[e];
    float r = gm.x, ux = gm.y, uy = gm.z, uz = gm.w;

    // hidden h (lane = hidden channel j)
    float x = edge_feat[(size_t)e * 32 + lane];
    float h = fmaf(r, sWr1[lane], sbr1[lane]);
#pragma unroll
    for (int i = 0; i < 32; i++) {
        float xi = __shfl_sync(FULLMASK, x, i);
        h = fmaf(xi, sWr1[(i + 1) * 32 + lane], h);
    }
    h = fmaxf(h, 0.f);

    // radial weights (lane = c)
    float w0 = 0.f, w1 = 0.f, w2 = 0.f, w3 = 0.f, w4 = 0.f, w5 = 0.f, w6 = 0.f;
#pragma unroll
    for (int j = 0; j < 32; j++) {
        float hj = __shfl_sync(FULLMASK, h, j);
        float4 a = sW2a[j * 32 + lane];
        if (FIRST) {
            w0 = fmaf(hj, a.x, w0);
            w3 = fmaf(hj, a.y, w3);
            w5 = fmaf(hj, a.z, w5);
        } else {
            float4 b = sW2b[j * 32 + lane];
            w0 = fmaf(hj, a.x, w0);
            w1 = fmaf(hj, a.y, w1);
            w2 = fmaf(hj, a.z, w2);
            w3 = fmaf(hj, a.w, w3);
            w4 = fmaf(hj, b.x, w4);
            w5 = fmaf(hj, b.y, w5);
            w6 = fmaf(hj, b.z, w6);
        }
    }

    float f0s = g_f0[(size_t)src * 32 + lane];
    float m0 = w0 * f0s;
    if (!FIRST) {
        const float* f1s = &g_f1[(size_t)src * 96 + lane * 3];
        const float* f2s = &g_f2[(size_t)src * 160 + lane * 5];
        float d1 = f1s[0] * ux + f1s[1] * uy + f1s[2] * uz;
        float s0 = ux * uy, s1 = uy * uz, s2 = 3.f * uz * uz - 1.f;
        float s3 = ux * uz, s4 = ux * ux - uy * uy;
        float d2 = f2s[0] * s0 + f2s[1] * s1 + f2s[2] * s2 + f2s[3] * s3 + f2s[4] * s4;
        m0 = fmaf(w1, d1, fmaf(w2, d2, m0));
    }
    g_m0[(size_t)e * 32 + lane] = m0;
    if (FIRST)
        ((float2*)g_w)[(size_t)e * 32 + lane] = make_float2(w3, w5);
    else
        ((float4*)g_w)[(size_t)e * 32 + lane] = make_float4(w3, w4, w5, w6);

    // k (lane = j)
    float k = 0.f;
#pragma unroll
    for (int c = 0; c < 32; c++) {
        float mc = __shfl_sync(FULLMASK, m0, c);
        k = fmaf(mc, sWk[c * 32 + lane], k);
    }
    float qv = g_q[(size_t)dst * 32 + lane];
    float p = qv * k;
    p += __shfl_xor_sync(FULLMASK, p, 1);
    p += __shfl_xor_sync(FULLMASK, p, 2);
    p += __shfl_xor_sync(FULLMASK, p, 4);
    if ((lane & 7) == 0)
        g_logit[(size_t)e * 4 + (lane >> 3)] = p * 0.35355339059327373f;  // 1/sqrt(8)
}

// Warp-per-node: segment softmax (max pass, then fused unnormalized accumulate + den)
// all per-edge reads coalesced; w3..w6 read back (no recompute).
template <bool FIRST>
__global__ __launch_bounds__(256) void agg_kernel(const int* __restrict__ esrc) {
    int tid = threadIdx.x;
    int lane = tid & 31;
    int n = blockIdx.x * 8 + (tid >> 5);
    if (n >= Nn) return;
    int beg = g_off[n], end = g_off[n + 1];
    int grp = lane >> 3;

    float mx = -3.0e38f;
    for (int i = beg; i < end; i++)
        mx = fmaxf(mx, g_logit[(size_t)g_eid[i] * 4 + grp]);

    float den = 0.f;
    float a0 = 0.f, a10 = 0.f, a11 = 0.f, a12 = 0.f;
    float a20 = 0.f, a21 = 0.f, a22 = 0.f, a23 = 0.f, a24 = 0.f;
#pragma unroll 2
    for (int i = beg; i < end; i++) {
        int eid = g_eid[i];
        float ee = __expf(g_logit[(size_t)eid * 4 + grp] - mx);
        den += ee;
        float m0 = g_m0[(size_t)eid * 32 + lane];
        float4 gm = ((const float4*)g_geom)[eid];
        float ux = gm.y, uy = gm.z, uz = gm.w;
        int src = esrc[eid];
        float f0s = g_f0[(size_t)src * 32 + lane];
        a0 = fmaf(ee, m0, a0);
        float y0 = ux * uy, y1 = uy * uz, y2 = 3.f * uz * uz - 1.f;
        float y3 = ux * uz, y4 = ux * ux - uy * uy;
        if (FIRST) {
            float2 w = ((const float2*)g_w)[(size_t)eid * 32 + lane];
            float wf3 = w.x * f0s * ee, wf5 = w.y * f0s * ee;
            a10 = fmaf(wf3, ux, a10); a11 = fmaf(wf3, uy, a11); a12 = fmaf(wf3, uz, a12);
            a20 = fmaf(wf5, y0, a20); a21 = fmaf(wf5, y1, a21); a22 = fmaf(wf5, y2, a22);
            a23 = fmaf(wf5, y3, a23); a24 = fmaf(wf5, y4, a24);
        } else {
            float4 w = ((const float4*)g_w)[(size_t)eid * 32 + lane];
            const float* f1s = &g_f1[(size_t)src * 96 + lane * 3];
            const float* f2s = &g_f2[(size_t)src * 160 + lane * 5];
            float wf3 = w.x * f0s * ee, ew4 = ee * w.y;
            float wf5 = w.z * f0s * ee, ew6 = ee * w.w;
            a10 += wf3 * ux + ew4 * f1s[0];
            a11 += wf3 * uy + ew4 * f1s[1];
            a12 += wf3 * uz + ew4 * f1s[2];
            a20 += wf5 * y0 + ew6 * f2s[0];
            a21 += wf5 * y1 + ew6 * f2s[1];
            a22 += wf5 * y2 + ew6 * f2s[2];
            a23 += wf5 * y3 + ew6 * f2s[3];
            a24 += wf5 * y4 + ew6 * f2s[4];
        }
    }
    float dinv = 1.f / (den + 1e-8f);
    float* ag = &g_agg[(size_t)n * 288 + lane * 9];
    ag[0] = a0 * dinv;
    ag[1] = a10 * dinv; ag[2] = a11 * dinv; ag[3] = a12 * dinv;
    ag[4] = a20 * dinv; ag[5] = a21 * dinv; ag[6] = a22 * dinv;
    ag[7] = a23 * dinv; ag[8] = a24 * dinv;
}

// Warp-per-node: f0' = agg0@Ws0 + f0@Wskip; f1'[o][m]=sum_c agg1[c][m]*Ws1[c][o]; f2' similar.
__global__ __launch_bounds__(256) void update_kernel(const float* __restrict__ Ws0,
                                                     const float* __restrict__ Ws1,
                                                     const float* __restrict__ Ws2,
                                                     const float* __restrict__ Wsk) {
    __shared__ __align__(16) float s0[1024], s1[1024], s2[1024], sk[1024];
    __shared__ float sag[8][288];
    int tid = threadIdx.x;
    for (int i = tid; i < 1024; i += 256) {
        s0[i] = Ws0[i]; s1[i] = Ws1[i]; s2[i] = Ws2[i]; sk[i] = Wsk[i];
    }
    __syncthreads();
    int warp = tid >> 5, lane = tid & 31;
    int n = blockIdx.x * 8 + warp;
    if (n >= Nn) return;
    float f = g_f0[(size_t)n * 32 + lane];
#pragma unroll
    for (int s = 0; s < 9; s++)
        sag[warp][lane * 9 + s] = g_agg[(size_t)n * 288 + lane * 9 + s];
    __syncwarp();
    float o0 = 0.f, o10 = 0.f, o11 = 0.f, o12 = 0.f;
    float o20 = 0.f, o21 = 0.f, o22 = 0.f, o23 = 0.f, o24 = 0.f;
#pragma unroll 4
    for (int c = 0; c < 32; c++) {
        const float* ac = &sag[warp][c * 9];
        float fc = __shfl_sync(FULLMASK, f, c);
        o0 += ac[0] * s0[c * 32 + lane] + fc * sk[c * 32 + lane];
        float w1 = s1[c * 32 + lane];
        o10 += ac[1] * w1; o11 += ac[2] * w1; o12 += ac[3] * w1;
        float w2 = s2[c * 32 + lane];
        o20 += ac[4] * w2; o21 += ac[5] * w2; o22 += ac[6] * w2;
        o23 += ac[7] * w2; o24 += ac[8] * w2;
    }
    g_f0[(size_t)n * 32 + lane] = o0;
    float* f1w = &g_f1[(size_t)n * 96 + lane * 3];
    f1w[0] = o10; f1w[1] = o11; f1w[2] = o12;
    float* f2w = &g_f2[(size_t)n * 160 + lane * 5];
    f2w[0] = o20; f2w[1] = o21; f2w[2] = o22; f2w[3] = o23; f2w[4] = o24;
}

// hs0 = f0@Wout -> out[0 : N*32);  cs = hs0@Wc -> out[N*32 : N*32+N*15)  (warp per node)
__global__ __launch_bounds__(256) void out_kernel(const float* __restrict__ Wout,
                                                  const float* __restrict__ Wc,
                                                  float* __restrict__ out) {
    __shared__ __align__(16) float sWo[1024];
    __shared__ float sWc[480];
    int tid = threadIdx.x;
    for (int i = tid; i < 1024; i += 256) sWo[i] = Wout[i];
    for (int i = tid; i < 480; i += 256) sWc[i] = Wc[i];
    __syncthreads();
    int warp = tid >> 5, lane = tid & 31;
    int n = blockIdx.x * 8 + warp;
    if (n >= Nn) return;
    float f = g_f0[(size_t)n * 32 + lane];
    float hs = 0.f;
#pragma unroll
    for (int c = 0; c < 32; c++) {
        float fc = __shfl_sync(FULLMASK, f, c);
        hs = fmaf(fc, sWo[c * 32 + lane], hs);
    }
    out[(size_t)n * 32 + lane] = hs;
    float cacc = 0.f;
#pragma unroll
    for (int j = 0; j < 32; j++) {
        float hj = __shfl_sync(FULLMASK, hs, j);
        if (lane < 15) cacc = fmaf(hj, sWc[j * 15 + lane], cacc);
    }
    if (lane < 15) out[(size_t)Nn * 32 + (size_t)n * 15 + lane] = cacc;
}

// ---------------- launch ----------------
extern "C" void kernel_launch(void* const* d_in, const int* in_sizes, int n_in,
                              void* d_out, int out_size) {
    const float* pos       = (const float*)d_in[0];
    const float* node_l0   = (const float*)d_in[1];
    const float* edge_feat = (const float*)d_in[2];
    const int*   esrc      = (const int*)d_in[3];
    const int*   edst      = (const int*)d_in[4];
    const float* Wr1       = (const float*)d_in[5];
    const float* br1       = (const float*)d_in[6];
    const float* Wr2       = (const float*)d_in[7];
    const float* Wq        = (const float*)d_in[8];
    const float* Wk        = (const float*)d_in[9];
    const float* Ws0       = (const float*)d_in[10];
    const float* Ws1       = (const float*)d_in[11];
    const float* Ws2       = (const float*)d_in[12];
    const float* Wsk       = (const float*)d_in[13];
    const float* Wout      = (const float*)d_in[14];
    const float* Wc        = (const float*)d_in[15];
    float* out = (float*)d_out;

    zero_deg_kernel<<<(Nn + 255) / 256, 256>>>();
    geom_hist_kernel<<<(Ee + 255) / 256, 256>>>(pos, esrc, edst);
    scan_kernel<<<1, 1024>>>();
    cursor_kernel<<<(Nn + 255) / 256, 256>>>();
    scatter_kernel<<<(Ee + 255) / 256, 256>>>(edst);
    copy_f0_kernel<<<(Nn * 32 + 255) / 256, 256>>>(node_l0);

    const int NODE_BLKS = (Nn + 7) / 8;   // warp-per-node kernels: 8 nodes / 256-thread block
    const int EDGE_BLKS = (Ee + 7) / 8;   // warp-per-edge kernels: 8 edges / 256-thread block
    // layer 0 (f1=f2=0 specialization)
    q_kernel<<<NODE_BLKS, 256>>>(Wq);
    edge_kernel<true><<<EDGE_BLKS, 256>>>(edge_feat, esrc, edst, Wr1, br1, Wr2, Wk);
    agg_kernel<true><<<NODE_BLKS, 256>>>(esrc);
    update_kernel<<<NODE_BLKS, 256>>>(Ws0, Ws1, Ws2, Wsk);
    // layer 1
    q_kernel<<<NODE_BLKS, 256>>>(Wq + 1024);
    edge_kernel<false><<<EDGE_BLKS, 256>>>(edge_feat, esrc, edst, Wr1 + 1056,
                                           br1 + 32, Wr2 + 7168, Wk + 1024);
    agg_kernel<false><<<NODE_BLKS, 256>>>(esrc);
    update_kernel<<<NODE_BLKS, 256>>>(Ws0 + 1024, Ws1 + 1024, Ws2 + 1024, Wsk + 1024);

    out_kernel<<<NODE_BLKS, 256>>>(Wout, Wc, out);
}

// round 4
// speedup vs baseline: 2.9289x; 1.8914x over previous
#include <cuda_runtime.h>

#define Nn 30000
#define Ee 480000
#define FULLMASK 0xffffffffu

typedef unsigned long long ull;

// packed fp32x2 helpers (Blackwell FFMA2 path — PTX only)
#define PACK2(d, lo, hi) asm("mov.b64 %0, {%1, %2};" : "=l"(d) : "f"(lo), "f"(hi))
#define UNPACK2(lo, hi, s) asm("mov.b64 {%0, %1}, %2;" : "=f"(lo), "=f"(hi) : "l"(s))
#define FMA2(acc, a, b) asm("fma.rn.f32x2 %0, %1, %2, %0;" : "+l"(acc) : "l"(a), "l"(b))

// ---------------- scratch (static device allocations; no cudaMalloc) ----------------
__device__ __align__(16) float g_geom[Ee * 4];   // r, ux, uy, uz
__device__ __align__(16) float g_m0[Ee * 32];
__device__ __align__(16) float g_w[Ee * 128];    // [E][32] float4 (w3,w4,w5,w6); layer0 float2 (w3,w5)
__device__ __align__(16) float g_logit[Ee * 4];
__device__ __align__(16) float g_kt[Nn * 128];   // [n][h][c]
__device__ float g_f0[Nn * 32];
__device__ float g_f1[Nn * 96];
__device__ float g_f2[Nn * 160];
__device__ float g_agg[Nn * 288];   // [n][c][9]
__device__ int g_deg[Nn];
__device__ int g_off[Nn + 1];
__device__ int g_cur[Nn];
__device__ int g_eid[Ee];

// ---------------- CSR build ----------------
__global__ void zero_deg_kernel() {
    int i = blockIdx.x * blockDim.x + threadIdx.x;
    if (i < Nn) g_deg[i] = 0;
}

__global__ void geom_hist_kernel(const float* __restrict__ pos,
                                 const int* __restrict__ esrc,
                                 const int* __restrict__ edst) {
    int e = blockIdx.x * blockDim.x + threadIdx.x;
    if (e >= Ee) return;
    int s = esrc[e], d = edst[e];
    float rx = pos[d * 3 + 0] - pos[s * 3 + 0];
    float ry = pos[d * 3 + 1] - pos[s * 3 + 1];
    float rz = pos[d * 3 + 2] - pos[s * 3 + 2];
    float r = sqrtf(rx * rx + ry * ry + rz * rz + 1e-8f);
    float inv = 1.0f / r;
    ((float4*)g_geom)[e] = make_float4(r, rx * inv, ry * inv, rz * inv);
    atomicAdd(&g_deg[d], 1);
}

__global__ void scan_kernel() {
    __shared__ int sp[1024];
    const int CH = 30;
    int t = threadIdx.x;
    int loc[CH];
    int base = t * CH;
    int s = 0;
#pragma unroll
    for (int i = 0; i < CH; i++) {
        int idx = base + i;
        int v = (idx < Nn) ? g_deg[idx] : 0;
        loc[i] = v;
        s += v;
    }
    sp[t] = s;
    __syncthreads();
    for (int off = 1; off < 1024; off <<= 1) {
        int v = (t >= off) ? sp[t - off] : 0;
        __syncthreads();
        sp[t] += v;
        __syncthreads();
    }
    int run = (t == 0) ? 0 : sp[t - 1];
#pragma unroll
    for (int i = 0; i < CH; i++) {
        int idx = base + i;
        if (idx < Nn) { g_off[idx] = run; run += loc[i]; }
    }
    if (t == 1023) g_off[Nn] = sp[1023];
}

__global__ void cursor_kernel() {
    int i = blockIdx.x * blockDim.x + threadIdx.x;
    if (i < Nn) g_cur[i] = g_off[i];
}

__global__ void scatter_kernel(const int* __restrict__ edst) {
    int e = blockIdx.x * blockDim.x + threadIdx.x;
    if (e >= Ee) return;
    int d = edst[e];
    int p = atomicAdd(&g_cur[d], 1);
    g_eid[p] = e;
}

__global__ void copy_f0_kernel(const float* __restrict__ src) {
    int i = blockIdx.x * blockDim.x + threadIdx.x;
    if (i < Nn * 32) g_f0[i] = src[i];
}

// ---------------- per-layer kernels ----------------
// K~[n][h][c] = sum_d Wk[c][h*8+d] * q[n][h*8+d], q = f0[n] @ Wq    (warp per node)
__global__ __launch_bounds__(256) void kt_kernel(const float* __restrict__ Wq,
                                                 const float* __restrict__ Wk) {
    __shared__ float sWq[1024];    // [c][j]
    __shared__ float sWkT[1024];   // [j][c] (transposed)
    int tid = threadIdx.x;
    for (int i = tid; i < 1024; i += 256) {
        sWq[i] = Wq[i];
        int c = i >> 5, j = i & 31;
        sWkT[j * 32 + c] = Wk[i];
    }
    __syncthreads();
    int warp = tid >> 5, lane = tid & 31;
    int n = blockIdx.x * 8 + warp;
    if (n >= Nn) return;
    float f = g_f0[(size_t)n * 32 + lane];
    float q = 0.f;
#pragma unroll
    for (int c = 0; c < 32; c++) {
        float fc = __shfl_sync(FULLMASK, f, c);
        q = fmaf(fc, sWq[c * 32 + lane], q);
    }
#pragma unroll
    for (int h = 0; h < 4; h++) {
        float kt = 0.f;
#pragma unroll
        for (int d = 0; d < 8; d++) {
            float qd = __shfl_sync(FULLMASK, q, h * 8 + d);
            kt = fmaf(qd, sWkT[(h * 8 + d) * 32 + lane], kt);
        }
        g_kt[(size_t)n * 128 + h * 32 + lane] = kt;
    }
}

// Warp-per-8-edges: radial MLP (packed f32x2), m0, w3..6, logits. lane = channel.
template <bool FIRST>
__global__ __launch_bounds__(256) void edge_kernel(
    const float* __restrict__ edge_feat, const int* __restrict__ esrc,
    const int* __restrict__ edst, const float* __restrict__ Wr1,
    const float* __restrict__ br1, const float* __restrict__ Wr2) {
    __shared__ __align__(16) float sWr1[33 * 32];
    __shared__ float sbr1[32];
    __shared__ __align__(16) float4 sW2a[1024];  // [j][c]: (p0,p1,p2,p3) | L0: (p0,p3,p5,-)
    __shared__ __align__(16) float4 sW2b[1024];  // [j][c]: (p4,p5,p6,-)  | L0 unused
    __shared__ __align__(16) float sstage[8][256];  // [warp][i*8+k]
    int tid = threadIdx.x;
    for (int i = tid; i < 33 * 32; i += 256) sWr1[i] = Wr1[i];
    if (tid < 32) sbr1[tid] = br1[tid];
    for (int i = tid; i < 1024; i += 256) {
        int j = i >> 5, c = i & 31;
        const float* row = Wr2 + j * 224;
        if (FIRST) {
            sW2a[i] = make_float4(row[c], row[96 + c], row[160 + c], 0.f);
        } else {
            sW2a[i] = make_float4(row[c], row[32 + c], row[64 + c], row[96 + c]);
            sW2b[i] = make_float4(row[128 + c], row[160 + c], row[192 + c], 0.f);
        }
    }
    __syncthreads();
    int lane = tid & 31, warp = tid >> 5;
    int e0 = blockIdx.x * 64 + warp * 8;   // Ee % 64 == 0
    float* sst = sstage[warp];

    // stage x transposed: sst[i*8+k] = edge_feat[e0+k][i]
    float t0, t1, t2, t3, t4, t5, t6, t7;
    t0 = edge_feat[(size_t)(e0 + 0) * 32 + lane];
    t1 = edge_feat[(size_t)(e0 + 1) * 32 + lane];
    t2 = edge_feat[(size_t)(e0 + 2) * 32 + lane];
    t3 = edge_feat[(size_t)(e0 + 3) * 32 + lane];
    t4 = edge_feat[(size_t)(e0 + 4) * 32 + lane];
    t5 = edge_feat[(size_t)(e0 + 5) * 32 + lane];
    t6 = edge_feat[(size_t)(e0 + 6) * 32 + lane];
    t7 = edge_feat[(size_t)(e0 + 7) * 32 + lane];
    {
        float4* sp = (float4*)(sst + lane * 8);
        sp[0] = make_float4(t0, t1, t2, t3);
        sp[1] = make_float4(t4, t5, t6, t7);
    }
    __syncwarp();

    // h init: bias + r * W1row0
    float bia = sbr1[lane], w0l = sWr1[lane];
    t0 = fmaf(g_geom[(size_t)(e0 + 0) * 4], w0l, bia);
    t1 = fmaf(g_geom[(size_t)(e0 + 1) * 4], w0l, bia);
    t2 = fmaf(g_geom[(size_t)(e0 + 2) * 4], w0l, bia);
    t3 = fmaf(g_geom[(size_t)(e0 + 3) * 4], w0l, bia);
    t4 = fmaf(g_geom[(size_t)(e0 + 4) * 4], w0l, bia);
    t5 = fmaf(g_geom[(size_t)(e0 + 5) * 4], w0l, bia);
    t6 = fmaf(g_geom[(size_t)(e0 + 6) * 4], w0l, bia);
    t7 = fmaf(g_geom[(size_t)(e0 + 7) * 4], w0l, bia);
    ull h01, h23, h45, h67;
    PACK2(h01, t0, t1); PACK2(h23, t2, t3); PACK2(h45, t4, t5); PACK2(h67, t6, t7);
#pragma unroll
    for (int i = 0; i < 32; i++) {
        const ull* xp = (const ull*)(sst + i * 8);
        ull x01 = xp[0], x23 = xp[1], x45 = xp[2], x67 = xp[3];
        float wc = sWr1[(i + 1) * 32 + lane];
        ull wd; PACK2(wd, wc, wc);
        FMA2(h01, x01, wd); FMA2(h23, x23, wd); FMA2(h45, x45, wd); FMA2(h67, x67, wd);
    }
    UNPACK2(t0, t1, h01); UNPACK2(t2, t3, h23); UNPACK2(t4, t5, h45); UNPACK2(t6, t7, h67);
    t0 = fmaxf(t0, 0.f); t1 = fmaxf(t1, 0.f); t2 = fmaxf(t2, 0.f); t3 = fmaxf(t3, 0.f);
    t4 = fmaxf(t4, 0.f); t5 = fmaxf(t5, 0.f); t6 = fmaxf(t6, 0.f); t7 = fmaxf(t7, 0.f);
    __syncwarp();
    {
        float4* sp = (float4*)(sst + lane * 8);
        sp[0] = make_float4(t0, t1, t2, t3);
        sp[1] = make_float4(t4, t5, t6, t7);
    }
    __syncwarp();

    // w-GEMM: w_p[c] for 8 edges, packed pairs
    ull ac0[4] = {0, 0, 0, 0}, ac1[4] = {0, 0, 0, 0}, ac2[4] = {0, 0, 0, 0},
        ac3[4] = {0, 0, 0, 0}, ac4[4] = {0, 0, 0, 0}, ac5[4] = {0, 0, 0, 0},
        ac6[4] = {0, 0, 0, 0};
#pragma unroll
    for (int j = 0; j < 32; j++) {
        const ull* hp = (const ull*)(sst + j * 8);
        ull p01 = hp[0], p23 = hp[1], p45 = hp[2], p67 = hp[3];
        float4 a = sW2a[j * 32 + lane];
        ull wa, wb, wc2;
        PACK2(wa, a.x, a.x); PACK2(wb, a.y, a.y); PACK2(wc2, a.z, a.z);
        if (FIRST) {
            // a = (p0, p3, p5, -)
            FMA2(ac0[0], p01, wa); FMA2(ac0[1], p23, wa); FMA2(ac0[2], p45, wa); FMA2(ac0[3], p67, wa);
            FMA2(ac3[0], p01, wb); FMA2(ac3[1], p23, wb); FMA2(ac3[2], p45, wb); FMA2(ac3[3], p67, wb);
            FMA2(ac5[0], p01, wc2); FMA2(ac5[1], p23, wc2); FMA2(ac5[2], p45, wc2); FMA2(ac5[3], p67, wc2);
        } else {
            float4 b = sW2b[j * 32 + lane];
            ull wd2, we, wf, wg;
            PACK2(wd2, a.w, a.w); PACK2(we, b.x, b.x); PACK2(wf, b.y, b.y); PACK2(wg, b.z, b.z);
            FMA2(ac0[0], p01, wa); FMA2(ac0[1], p23, wa); FMA2(ac0[2], p45, wa); FMA2(ac0[3], p67, wa);
            FMA2(ac1[0], p01, wb); FMA2(ac1[1], p23, wb); FMA2(ac1[2], p45, wb); FMA2(ac1[3], p67, wb);
            FMA2(ac2[0], p01, wc2); FMA2(ac2[1], p23, wc2); FMA2(ac2[2], p45, wc2); FMA2(ac2[3], p67, wc2);
            FMA2(ac3[0], p01, wd2); FMA2(ac3[1], p23, wd2); FMA2(ac3[2], p45, wd2); FMA2(ac3[3], p67, wd2);
            FMA2(ac4[0], p01, we); FMA2(ac4[1], p23, we); FMA2(ac4[2], p45, we); FMA2(ac4[3], p67, we);
            FMA2(ac5[0], p01, wf); FMA2(ac5[1], p23, wf); FMA2(ac5[2], p45, wf); FMA2(ac5[3], p67, wf);
            FMA2(ac6[0], p01, wg); FMA2(ac6[1], p23, wg); FMA2(ac6[2], p45, wg); FMA2(ac6[3], p67, wg);
        }
    }

    // tail: m0, stores, logits (per edge)
#pragma unroll
    for (int q2 = 0; q2 < 4; q2++) {
        float W0a, W0b, W1a = 0.f, W1b = 0.f, W2a = 0.f, W2b = 0.f;
        float W3a, W3b, W4a = 0.f, W4b = 0.f, W5a, W5b, W6a = 0.f, W6b = 0.f;
        UNPACK2(W0a, W0b, ac0[q2]);
        UNPACK2(W3a, W3b, ac3[q2]);
        UNPACK2(W5a, W5b, ac5[q2]);
        if (!FIRST) {
            UNPACK2(W1a, W1b, ac1[q2]);
            UNPACK2(W2a, W2b, ac2[q2]);
            UNPACK2(W4a, W4b, ac4[q2]);
            UNPACK2(W6a, W6b, ac6[q2]);
        }
#pragma unroll
        for (int kk = 0; kk < 2; kk++) {
            int e = e0 + q2 * 2 + kk;
            float W0 = kk ? W0b : W0a, W1 = kk ? W1b : W1a, W2 = kk ? W2b : W2a;
            float W3 = kk ? W3b : W3a, W4 = kk ? W4b : W4a, W5 = kk ? W5b : W5a;
            float W6 = kk ? W6b : W6a;
            int src = esrc[e], dst = edst[e];
            float f0s = g_f0[(size_t)src * 32 + lane];
            float m0;
            if (FIRST) {
                m0 = W0 * f0s;
            } else {
                float4 gm = ((const float4*)g_geom)[e];
                float ux = gm.y, uy = gm.z, uz = gm.w;
                const float* f1p = &g_f1[(size_t)src * 96 + lane * 3];
                const float* f2p = &g_f2[(size_t)src * 160 + lane * 5];
                float d1 = f1p[0] * ux + f1p[1] * uy + f1p[2] * uz;
                float s0 = ux * uy, s1 = uy * uz, s2 = 3.f * uz * uz - 1.f;
                float s3 = ux * uz, s4 = ux * ux - uy * uy;
                float d2 = f2p[0] * s0 + f2p[1] * s1 + f2p[2] * s2 + f2p[3] * s3 + f2p[4] * s4;
                m0 = fmaf(W1, d1, fmaf(W2, d2, W0 * f0s));
            }
            g_m0[(size_t)e * 32 + lane] = m0;
            if (FIRST)
                ((float2*)g_w)[(size_t)e * 32 + lane] = make_float2(W3, W5);
            else
                ((float4*)g_w)[(size_t)e * 32 + lane] = make_float4(W3, W4, W5, W6);
            const float* ktp = &g_kt[(size_t)dst * 128];
            float lg = 0.f;
#pragma unroll
            for (int h = 0; h < 4; h++) {
                float v = m0 * ktp[h * 32 + lane];
                v += __shfl_xor_sync(FULLMASK, v, 16);
                v += __shfl_xor_sync(FULLMASK, v, 8);
                v += __shfl_xor_sync(FULLMASK, v, 4);
                v += __shfl_xor_sync(FULLMASK, v, 2);
                v += __shfl_xor_sync(FULLMASK, v, 1);
                if (lane == h) lg = v;
            }
            if (lane < 4)
                g_logit[(size_t)e * 4 + lane] = lg * 0.35355339059327373f;
        }
    }
}

// Warp-per-node: segment softmax + fused aggregation (coalesced streams).
template <bool FIRST>
__global__ __launch_bounds__(256) void agg_kernel(const int* __restrict__ esrc) {
    int tid = threadIdx.x;
    int lane = tid & 31;
    int n = blockIdx.x * 8 + (tid >> 5);
    if (n >= Nn) return;
    int beg = g_off[n], end = g_off[n + 1];
    int grp = lane >> 3;

    float mx = -3.0e38f;
    for (int i = beg; i < end; i++)
        mx = fmaxf(mx, g_logit[(size_t)g_eid[i] * 4 + grp]);

    float den = 0.f;
    float a0 = 0.f, a10 = 0.f, a11 = 0.f, a12 = 0.f;
    float a20 = 0.f, a21 = 0.f, a22 = 0.f, a23 = 0.f, a24 = 0.f;
#pragma unroll 2
    for (int i = beg; i < end; i++) {
        int eid = g_eid[i];
        float ee = __expf(g_logit[(size_t)eid * 4 + grp] - mx);
        den += ee;
        float m0 = g_m0[(size_t)eid * 32 + lane];
        float4 gm = ((const float4*)g_geom)[eid];
        float ux = gm.y, uy = gm.z, uz = gm.w;
        int src = esrc[eid];
        float f0s = g_f0[(size_t)src * 32 + lane];
        a0 = fmaf(ee, m0, a0);
        float y0 = ux * uy, y1 = uy * uz, y2 = 3.f * uz * uz - 1.f;
        float y3 = ux * uz, y4 = ux * ux - uy * uy;
        if (FIRST) {
            float2 w = ((const float2*)g_w)[(size_t)eid * 32 + lane];
            float wf3 = w.x * f0s * ee, wf5 = w.y * f0s * ee;
            a10 = fmaf(wf3, ux, a10); a11 = fmaf(wf3, uy, a11); a12 = fmaf(wf3, uz, a12);
            a20 = fmaf(wf5, y0, a20); a21 = fmaf(wf5, y1, a21); a22 = fmaf(wf5, y2, a22);
            a23 = fmaf(wf5, y3, a23); a24 = fmaf(wf5, y4, a24);
        } else {
            float4 w = ((const float4*)g_w)[(size_t)eid * 32 + lane];
            const float* f1s = &g_f1[(size_t)src * 96 + lane * 3];
            const float* f2s = &g_f2[(size_t)src * 160 + lane * 5];
            float wf3 = w.x * f0s * ee, ew4 = ee * w.y;
            float wf5 = w.z * f0s * ee, ew6 = ee * w.w;
            a10 += wf3 * ux + ew4 * f1s[0];
            a11 += wf3 * uy + ew4 * f1s[1];
            a12 += wf3 * uz + ew4 * f1s[2];
            a20 += wf5 * y0 + ew6 * f2s[0];
            a21 += wf5 * y1 + ew6 * f2s[1];
            a22 += wf5 * y2 + ew6 * f2s[2];
            a23 += wf5 * y3 + ew6 * f2s[3];
            a24 += wf5 * y4 + ew6 * f2s[4];
        }
    }
    float dinv = 1.f / (den + 1e-8f);
    float* ag = &g_agg[(size_t)n * 288 + lane * 9];
    ag[0] = a0 * dinv;
    ag[1] = a10 * dinv; ag[2] = a11 * dinv; ag[3] = a12 * dinv;
    ag[4] = a20 * dinv; ag[5] = a21 * dinv; ag[6] = a22 * dinv;
    ag[7] = a23 * dinv; ag[8] = a24 * dinv;
}

// Warp-per-node node update.
__global__ __launch_bounds__(256) void update_kernel(const float* __restrict__ Ws0,
                                                     const float* __restrict__ Ws1,
                                                     const float* __restrict__ Ws2,
                                                     const float* __restrict__ Wsk) {
    __shared__ __align__(16) float s0[1024], s1[1024], s2[1024], sk[1024];
    __shared__ float sag[8][288];
    int tid = threadIdx.x;
    for (int i = tid; i < 1024; i += 256) {
        s0[i] = Ws0[i]; s1[i] = Ws1[i]; s2[i] = Ws2[i]; sk[i] = Wsk[i];
    }
    __syncthreads();
    int warp = tid >> 5, lane = tid & 31;
    int n = blockIdx.x * 8 + warp;
    if (n >= Nn) return;
    float f = g_f0[(size_t)n * 32 + lane];
#pragma unroll
    for (int s = 0; s < 9; s++)
        sag[warp][lane * 9 + s] = g_agg[(size_t)n * 288 + lane * 9 + s];
    __syncwarp();
    float o0 = 0.f, o10 = 0.f, o11 = 0.f, o12 = 0.f;
    float o20 = 0.f, o21 = 0.f, o22 = 0.f, o23 = 0.f, o24 = 0.f;
#pragma unroll 4
    for (int c = 0; c < 32; c++) {
        const float* ac = &sag[warp][c * 9];
        float fc = __shfl_sync(FULLMASK, f, c);
        o0 += ac[0] * s0[c * 32 + lane] + fc * sk[c * 32 + lane];
        float w1 = s1[c * 32 + lane];
        o10 += ac[1] * w1; o11 += ac[2] * w1; o12 += ac[3] * w1;
        float w2 = s2[c * 32 + lane];
        o20 += ac[4] * w2; o21 += ac[5] * w2; o22 += ac[6] * w2;
        o23 += ac[7] * w2; o24 += ac[8] * w2;
    }
    g_f0[(size_t)n * 32 + lane] = o0;
    float* f1w = &g_f1[(size_t)n * 96 + lane * 3];
    f1w[0] = o10; f1w[1] = o11; f1w[2] = o12;
    float* f2w = &g_f2[(size_t)n * 160 + lane * 5];
    f2w[0] = o20; f2w[1] = o21; f2w[2] = o22; f2w[3] = o23; f2w[4] = o24;
}

// hs0 = f0@Wout; cs = hs0@Wc   (warp per node)
__global__ __launch_bounds__(256) void out_kernel(const float* __restrict__ Wout,
                                                  const float* __restrict__ Wc,
                                                  float* __restrict__ out) {
    __shared__ __align__(16) float sWo[1024];
    __shared__ float sWc[480];
    int tid = threadIdx.x;
    for (int i = tid; i < 1024; i += 256) sWo[i] = Wout[i];
    for (int i = tid; i < 480; i += 256) sWc[i] = Wc[i];
    __syncthreads();
    int warp = tid >> 5, lane = tid & 31;
    int n = blockIdx.x * 8 + warp;
    if (n >= Nn) return;
    float f = g_f0[(size_t)n * 32 + lane];
    float hs = 0.f;
#pragma unroll
    for (int c = 0; c < 32; c++) {
        float fc = __shfl_sync(FULLMASK, f, c);
        hs = fmaf(fc, sWo[c * 32 + lane], hs);
    }
    out[(size_t)n * 32 + lane] = hs;
    float cacc = 0.f;
#pragma unroll
    for (int j = 0; j < 32; j++) {
        float hj = __shfl_sync(FULLMASK, hs, j);
        if (lane < 15) cacc = fmaf(hj, sWc[j * 15 + lane], cacc);
    }
    if (lane < 15) out[(size_t)Nn * 32 + (size_t)n * 15 + lane] = cacc;
}

// ---------------- launch ----------------
extern "C" void kernel_launch(void* const* d_in, const int* in_sizes, int n_in,
                              void* d_out, int out_size) {
    const float* pos       = (const float*)d_in[0];
    const float* node_l0   = (const float*)d_in[1];
    const float* edge_feat = (const float*)d_in[2];
    const int*   esrc      = (const int*)d_in[3];
    const int*   edst      = (const int*)d_in[4];
    const float* Wr1       = (const float*)d_in[5];
    const float* br1       = (const float*)d_in[6];
    const float* Wr2       = (const float*)d_in[7];
    const float* Wq        = (const float*)d_in[8];
    const float* Wk        = (const float*)d_in[9];
    const float* Ws0       = (const float*)d_in[10];
    const float* Ws1       = (const float*)d_in[11];
    const float* Ws2       = (const float*)d_in[12];
    const float* Wsk       = (const float*)d_in[13];
    const float* Wout      = (const float*)d_in[14];
    const float* Wc        = (const float*)d_in[15];
    float* out = (float*)d_out;

    zero_deg_kernel<<<(Nn + 255) / 256, 256>>>();
    geom_hist_kernel<<<(Ee + 255) / 256, 256>>>(pos, esrc, edst);
    scan_kernel<<<1, 1024>>>();
    cursor_kernel<<<(Nn + 255) / 256, 256>>>();
    scatter_kernel<<<(Ee + 255) / 256, 256>>>(edst);
    copy_f0_kernel<<<(Nn * 32 + 255) / 256, 256>>>(node_l0);

    const int NODE_BLKS = (Nn + 7) / 8;    // warp-per-node: 8 nodes / block
    const int EDGE_BLKS = Ee / 64;         // warp-per-8-edges: 64 edges / block
    // layer 0 (f1=f2=0 specialization)
    kt_kernel<<<NODE_BLKS, 256>>>(Wq, Wk);
    edge_kernel<true><<<EDGE_BLKS, 256>>>(edge_feat, esrc, edst, Wr1, br1, Wr2);
    agg_kernel<true><<<NODE_BLKS, 256>>>(esrc);
    update_kernel<<<NODE_BLKS, 256>>>(Ws0, Ws1, Ws2, Wsk);
    // layer 1
    kt_kernel<<<NODE_BLKS, 256>>>(Wq + 1024, Wk + 1024);
    edge_kernel<false><<<EDGE_BLKS, 256>>>(edge_feat, esrc, edst, Wr1 + 1056,
                                           br1 + 32, Wr2 + 7168);
    agg_kernel<false><<<NODE_BLKS, 256>>>(esrc);
    update_kernel<<<NODE_BLKS, 256>>>(Ws0 + 1024, Ws1 + 1024, Ws2 + 1024, Wsk + 1024);

    out_kernel<<<NODE_BLKS, 256>>>(Wout, Wc, out);
}

// round 5
// speedup vs baseline: 4.0026x; 1.3666x over previous
#include <cuda_runtime.h>

#define Nn 30000
#define Ee 480000
#define FULLMASK 0xffffffffu

typedef unsigned long long ull;

// packed fp32x2 helpers (Blackwell FFMA2 path — PTX only)
#define PACK2(d, lo, hi) asm("mov.b64 %0, {%1, %2};" : "=l"(d) : "f"(lo), "f"(hi))
#define UNPACK2(lo, hi, s) asm("mov.b64 {%0, %1}, %2;" : "=f"(lo), "=f"(hi) : "l"(s))
#define FMA2(acc, a, b) asm("fma.rn.f32x2 %0, %1, %2, %0;" : "+l"(acc) : "l"(a), "l"(b))

// ---------------- scratch (static device allocations; no cudaMalloc) ----------------
__device__ __align__(16) float g_geom[Ee * 4];   // r, ux, uy, uz
__device__ __align__(16) float g_m0[Ee * 32];
__device__ __align__(16) float g_w[Ee * 64];     // layer0 only: [E][32] float2 (w3,w5)
__device__ __align__(16) float g_logit[Ee * 4];
__device__ __align__(16) float g_kt[Nn * 128];   // [n][h][c]
__device__ float g_f0[Nn * 32];
__device__ float g_f1[Nn * 96];
__device__ float g_f2[Nn * 160];
__device__ float g_agg[Nn * 288];   // layer0: [n][c][9]
__device__ float g_agg0[Nn * 32];   // layer1: [n][c]
__device__ int g_deg[Nn];
__device__ int g_off[Nn + 1];
__device__ int g_cur[Nn];
__device__ int g_eid[Ee];

// ---------------- 1) init: copy f0, zero deg, kt for layer 0 (warp per node) ----------------
__global__ __launch_bounds__(256) void init_kt_kernel(const float* __restrict__ node_l0,
                                                      const float* __restrict__ Wq,
                                                      const float* __restrict__ Wk) {
    __shared__ float sWq[1024];    // [c][j]
    __shared__ float sWkT[1024];   // [j][c]
    int tid = threadIdx.x;
    for (int i = tid; i < 1024; i += 256) {
        sWq[i] = Wq[i];
        int c = i >> 5, j = i & 31;
        sWkT[j * 32 + c] = Wk[i];
    }
    __syncthreads();
    int warp = tid >> 5, lane = tid & 31;
    int n = blockIdx.x * 8 + warp;
    if (n >= Nn) return;
    float f = node_l0[(size_t)n * 32 + lane];
    g_f0[(size_t)n * 32 + lane] = f;
    if (lane == 0) g_deg[n] = 0;
    float q = 0.f;
#pragma unroll
    for (int c = 0; c < 32; c++) {
        float fc = __shfl_sync(FULLMASK, f, c);
        q = fmaf(fc, sWq[c * 32 + lane], q);
    }
#pragma unroll
    for (int h = 0; h < 4; h++) {
        float kt = 0.f;
#pragma unroll
        for (int d = 0; d < 8; d++) {
            float qd = __shfl_sync(FULLMASK, q, h * 8 + d);
            kt = fmaf(qd, sWkT[(h * 8 + d) * 32 + lane], kt);
        }
        g_kt[(size_t)n * 128 + h * 32 + lane] = kt;
    }
}

// ---------------- 2) geometry + degree histogram ----------------
__global__ void geom_hist_kernel(const float* __restrict__ pos,
                                 const int* __restrict__ esrc,
                                 const int* __restrict__ edst) {
    int e = blockIdx.x * blockDim.x + threadIdx.x;
    if (e >= Ee) return;
    int s = esrc[e], d = edst[e];
    float rx = pos[d * 3 + 0] - pos[s * 3 + 0];
    float ry = pos[d * 3 + 1] - pos[s * 3 + 1];
    float rz = pos[d * 3 + 2] - pos[s * 3 + 2];
    float r = sqrtf(rx * rx + ry * ry + rz * rz + 1e-8f);
    float inv = 1.0f / r;
    ((float4*)g_geom)[e] = make_float4(r, rx * inv, ry * inv, rz * inv);
    atomicAdd(&g_deg[d], 1);
}

// ---------------- 3) exclusive scan (writes g_off and g_cur) ----------------
__global__ void scan_kernel() {
    __shared__ int sp[1024];
    const int CH = 30;
    int t = threadIdx.x;
    int loc[CH];
    int base = t * CH;
    int s = 0;
#pragma unroll
    for (int i = 0; i < CH; i++) {
        int idx = base + i;
        int v = (idx < Nn) ? g_deg[idx] : 0;
        loc[i] = v;
        s += v;
    }
    sp[t] = s;
    __syncthreads();
    for (int off = 1; off < 1024; off <<= 1) {
        int v = (t >= off) ? sp[t - off] : 0;
        __syncthreads();
        sp[t] += v;
        __syncthreads();
    }
    int run = (t == 0) ? 0 : sp[t - 1];
#pragma unroll
    for (int i = 0; i < CH; i++) {
        int idx = base + i;
        if (idx < Nn) { g_off[idx] = run; g_cur[idx] = run; run += loc[i]; }
    }
    if (t == 1023) g_off[Nn] = sp[1023];
}

// ---------------- 5) scatter edge ids by dst ----------------
__global__ void scatter_kernel(const int* __restrict__ edst) {
    int e = blockIdx.x * blockDim.x + threadIdx.x;
    if (e >= Ee) return;
    int d = edst[e];
    int p = atomicAdd(&g_cur[d], 1);
    g_eid[p] = e;
}

// ---------------- 4) layer-0 edge kernel (warp per 8 edges; f1=f2=0) ----------------
__global__ __launch_bounds__(256) void edge_l0_kernel(
    const float* __restrict__ edge_feat, const int* __restrict__ esrc,
    const int* __restrict__ edst, const float* __restrict__ Wr1,
    const float* __restrict__ br1, const float* __restrict__ Wr2) {
    __shared__ __align__(16) float sWr1[33 * 32];
    __shared__ float sbr1[32];
    __shared__ __align__(16) float4 sW2a[1024];  // [j][c]: (p0,p3,p5,-)
    __shared__ __align__(16) float sstage[8][256];
    int tid = threadIdx.x;
    for (int i = tid; i < 33 * 32; i += 256) sWr1[i] = Wr1[i];
    if (tid < 32) sbr1[tid] = br1[tid];
    for (int i = tid; i < 1024; i += 256) {
        int j = i >> 5, c = i & 31;
        const float* row = Wr2 + j * 224;
        sW2a[i] = make_float4(row[c], row[96 + c], row[160 + c], 0.f);
    }
    __syncthreads();
    int lane = tid & 31, warp = tid >> 5;
    int e0 = blockIdx.x * 64 + warp * 8;
    float* sst = sstage[warp];

    float t0, t1, t2, t3, t4, t5, t6, t7;
    t0 = edge_feat[(size_t)(e0 + 0) * 32 + lane];
    t1 = edge_feat[(size_t)(e0 + 1) * 32 + lane];
    t2 = edge_feat[(size_t)(e0 + 2) * 32 + lane];
    t3 = edge_feat[(size_t)(e0 + 3) * 32 + lane];
    t4 = edge_feat[(size_t)(e0 + 4) * 32 + lane];
    t5 = edge_feat[(size_t)(e0 + 5) * 32 + lane];
    t6 = edge_feat[(size_t)(e0 + 6) * 32 + lane];
    t7 = edge_feat[(size_t)(e0 + 7) * 32 + lane];
    {
        float4* sp = (float4*)(sst + lane * 8);
        sp[0] = make_float4(t0, t1, t2, t3);
        sp[1] = make_float4(t4, t5, t6, t7);
    }
    __syncwarp();

    float bia = sbr1[lane], w0l = sWr1[lane];
    t0 = fmaf(g_geom[(size_t)(e0 + 0) * 4], w0l, bia);
    t1 = fmaf(g_geom[(size_t)(e0 + 1) * 4], w0l, bia);
    t2 = fmaf(g_geom[(size_t)(e0 + 2) * 4], w0l, bia);
    t3 = fmaf(g_geom[(size_t)(e0 + 3) * 4], w0l, bia);
    t4 = fmaf(g_geom[(size_t)(e0 + 4) * 4], w0l, bia);
    t5 = fmaf(g_geom[(size_t)(e0 + 5) * 4], w0l, bia);
    t6 = fmaf(g_geom[(size_t)(e0 + 6) * 4], w0l, bia);
    t7 = fmaf(g_geom[(size_t)(e0 + 7) * 4], w0l, bia);
    ull h01, h23, h45, h67;
    PACK2(h01, t0, t1); PACK2(h23, t2, t3); PACK2(h45, t4, t5); PACK2(h67, t6, t7);
#pragma unroll
    for (int i = 0; i < 32; i++) {
        const ull* xp = (const ull*)(sst + i * 8);
        ull x01 = xp[0], x23 = xp[1], x45 = xp[2], x67 = xp[3];
        float wc = sWr1[(i + 1) * 32 + lane];
        ull wd; PACK2(wd, wc, wc);
        FMA2(h01, x01, wd); FMA2(h23, x23, wd); FMA2(h45, x45, wd); FMA2(h67, x67, wd);
    }
    UNPACK2(t0, t1, h01); UNPACK2(t2, t3, h23); UNPACK2(t4, t5, h45); UNPACK2(t6, t7, h67);
    t0 = fmaxf(t0, 0.f); t1 = fmaxf(t1, 0.f); t2 = fmaxf(t2, 0.f); t3 = fmaxf(t3, 0.f);
    t4 = fmaxf(t4, 0.f); t5 = fmaxf(t5, 0.f); t6 = fmaxf(t6, 0.f); t7 = fmaxf(t7, 0.f);
    __syncwarp();
    {
        float4* sp = (float4*)(sst + lane * 8);
        sp[0] = make_float4(t0, t1, t2, t3);
        sp[1] = make_float4(t4, t5, t6, t7);
    }
    __syncwarp();

    ull ac0[4] = {0, 0, 0, 0}, ac3[4] = {0, 0, 0, 0}, ac5[4] = {0, 0, 0, 0};
#pragma unroll
    for (int j = 0; j < 32; j++) {
        const ull* hp = (const ull*)(sst + j * 8);
        ull p01 = hp[0], p23 = hp[1], p45 = hp[2], p67 = hp[3];
        float4 a = sW2a[j * 32 + lane];
        ull wa, wb, wc2;
        PACK2(wa, a.x, a.x); PACK2(wb, a.y, a.y); PACK2(wc2, a.z, a.z);
        FMA2(ac0[0], p01, wa); FMA2(ac0[1], p23, wa); FMA2(ac0[2], p45, wa); FMA2(ac0[3], p67, wa);
        FMA2(ac3[0], p01, wb); FMA2(ac3[1], p23, wb); FMA2(ac3[2], p45, wb); FMA2(ac3[3], p67, wb);
        FMA2(ac5[0], p01, wc2); FMA2(ac5[1], p23, wc2); FMA2(ac5[2], p45, wc2); FMA2(ac5[3], p67, wc2);
    }

#pragma unroll
    for (int q2 = 0; q2 < 4; q2++) {
        float W0a, W0b, W3a, W3b, W5a, W5b;
        UNPACK2(W0a, W0b, ac0[q2]);
        UNPACK2(W3a, W3b, ac3[q2]);
        UNPACK2(W5a, W5b, ac5[q2]);
#pragma unroll
        for (int kk = 0; kk < 2; kk++) {
            int e = e0 + q2 * 2 + kk;
            float W0 = kk ? W0b : W0a, W3 = kk ? W3b : W3a, W5 = kk ? W5b : W5a;
            int src = esrc[e], dst = edst[e];
            float f0s = g_f0[(size_t)src * 32 + lane];
            float m0 = W0 * f0s;
            g_m0[(size_t)e * 32 + lane] = m0;
            ((float2*)g_w)[(size_t)e * 32 + lane] = make_float2(W3, W5);
            const float* ktp = &g_kt[(size_t)dst * 128];
            float lg = 0.f;
#pragma unroll
            for (int h = 0; h < 4; h++) {
                float v = m0 * ktp[h * 32 + lane];
                v += __shfl_xor_sync(FULLMASK, v, 16);
                v += __shfl_xor_sync(FULLMASK, v, 8);
                v += __shfl_xor_sync(FULLMASK, v, 4);
                v += __shfl_xor_sync(FULLMASK, v, 2);
                v += __shfl_xor_sync(FULLMASK, v, 1);
                if (lane == h) lg = v;
            }
            if (lane < 4)
                g_logit[(size_t)e * 4 + lane] = lg * 0.35355339059327373f;
        }
    }
}

// ---------------- 6) layer-0 aggregation (warp per node) ----------------
__global__ __launch_bounds__(256) void agg_l0_kernel(const int* __restrict__ esrc) {
    int tid = threadIdx.x;
    int lane = tid & 31;
    int n = blockIdx.x * 8 + (tid >> 5);
    if (n >= Nn) return;
    int beg = g_off[n], end = g_off[n + 1];
    int grp = lane >> 3;

    float mx = -3.0e38f;
    for (int i = beg; i < end; i++)
        mx = fmaxf(mx, g_logit[(size_t)g_eid[i] * 4 + grp]);

    float den = 0.f;
    float a0 = 0.f, a10 = 0.f, a11 = 0.f, a12 = 0.f;
    float a20 = 0.f, a21 = 0.f, a22 = 0.f, a23 = 0.f, a24 = 0.f;
#pragma unroll 2
    for (int i = beg; i < end; i++) {
        int eid = g_eid[i];
        float ee = __expf(g_logit[(size_t)eid * 4 + grp] - mx);
        den += ee;
        float m0 = g_m0[(size_t)eid * 32 + lane];
        float4 gm = ((const float4*)g_geom)[eid];
        float ux = gm.y, uy = gm.z, uz = gm.w;
        int src = esrc[eid];
        float f0s = g_f0[(size_t)src * 32 + lane];
        a0 = fmaf(ee, m0, a0);
        float y0 = ux * uy, y1 = uy * uz, y2 = 3.f * uz * uz - 1.f;
        float y3 = ux * uz, y4 = ux * ux - uy * uy;
        float2 w = ((const float2*)g_w)[(size_t)eid * 32 + lane];
        float wf3 = w.x * f0s * ee, wf5 = w.y * f0s * ee;
        a10 = fmaf(wf3, ux, a10); a11 = fmaf(wf3, uy, a11); a12 = fmaf(wf3, uz, a12);
        a20 = fmaf(wf5, y0, a20); a21 = fmaf(wf5, y1, a21); a22 = fmaf(wf5, y2, a22);
        a23 = fmaf(wf5, y3, a23); a24 = fmaf(wf5, y4, a24);
    }
    float dinv = 1.f / (den + 1e-8f);
    float* ag = &g_agg[(size_t)n * 288 + lane * 9];
    ag[0] = a0 * dinv;
    ag[1] = a10 * dinv; ag[2] = a11 * dinv; ag[3] = a12 * dinv;
    ag[4] = a20 * dinv; ag[5] = a21 * dinv; ag[6] = a22 * dinv;
    ag[7] = a23 * dinv; ag[8] = a24 * dinv;
}

// ---------------- 7) layer-0 update (writes f0,f1,f2) + kt for layer 1 ----------------
__global__ __launch_bounds__(256) void update_l0_kt_kernel(
    const float* __restrict__ Ws0, const float* __restrict__ Ws1,
    const float* __restrict__ Ws2, const float* __restrict__ Wsk,
    const float* __restrict__ Wq, const float* __restrict__ Wk) {
    __shared__ __align__(16) float s0[1024], s1[1024], s2[1024], sk[1024];
    __shared__ float sWq[1024], sWkT[1024];
    __shared__ float sag[8][288];
    int tid = threadIdx.x;
    for (int i = tid; i < 1024; i += 256) {
        s0[i] = Ws0[i]; s1[i] = Ws1[i]; s2[i] = Ws2[i]; sk[i] = Wsk[i];
        sWq[i] = Wq[i];
        int c = i >> 5, j = i & 31;
        sWkT[j * 32 + c] = Wk[i];
    }
    __syncthreads();
    int warp = tid >> 5, lane = tid & 31;
    int n = blockIdx.x * 8 + warp;
    if (n >= Nn) return;
    float f = g_f0[(size_t)n * 32 + lane];
#pragma unroll
    for (int s = 0; s < 9; s++)
        sag[warp][lane * 9 + s] = g_agg[(size_t)n * 288 + lane * 9 + s];
    __syncwarp();
    float o0 = 0.f, o10 = 0.f, o11 = 0.f, o12 = 0.f;
    float o20 = 0.f, o21 = 0.f, o22 = 0.f, o23 = 0.f, o24 = 0.f;
#pragma unroll 4
    for (int c = 0; c < 32; c++) {
        const float* ac = &sag[warp][c * 9];
        float fc = __shfl_sync(FULLMASK, f, c);
        o0 += ac[0] * s0[c * 32 + lane] + fc * sk[c * 32 + lane];
        float w1 = s1[c * 32 + lane];
        o10 += ac[1] * w1; o11 += ac[2] * w1; o12 += ac[3] * w1;
        float w2 = s2[c * 32 + lane];
        o20 += ac[4] * w2; o21 += ac[5] * w2; o22 += ac[6] * w2;
        o23 += ac[7] * w2; o24 += ac[8] * w2;
    }
    g_f0[(size_t)n * 32 + lane] = o0;
    float* f1w = &g_f1[(size_t)n * 96 + lane * 3];
    f1w[0] = o10; f1w[1] = o11; f1w[2] = o12;
    float* f2w = &g_f2[(size_t)n * 160 + lane * 5];
    f2w[0] = o20; f2w[1] = o21; f2w[2] = o22; f2w[3] = o23; f2w[4] = o24;
    // kt for layer 1 from updated f0
    float q = 0.f;
#pragma unroll
    for (int c = 0; c < 32; c++) {
        float fc = __shfl_sync(FULLMASK, o0, c);
        q = fmaf(fc, sWq[c * 32 + lane], q);
    }
#pragma unroll
    for (int h = 0; h < 4; h++) {
        float kt = 0.f;
#pragma unroll
        for (int d = 0; d < 8; d++) {
            float qd = __shfl_sync(FULLMASK, q, h * 8 + d);
            kt = fmaf(qd, sWkT[(h * 8 + d) * 32 + lane], kt);
        }
        g_kt[(size_t)n * 128 + h * 32 + lane] = kt;
    }
}

// ---------------- 8) layer-1 edge kernel (only w0,w1,w2 — agg1/agg2 are dead) ----------------
__global__ __launch_bounds__(256) void edge_l1_kernel(
    const float* __restrict__ edge_feat, const int* __restrict__ esrc,
    const int* __restrict__ edst, const float* __restrict__ Wr1,
    const float* __restrict__ br1, const float* __restrict__ Wr2) {
    __shared__ __align__(16) float sWr1[33 * 32];
    __shared__ float sbr1[32];
    __shared__ __align__(16) float4 sW2a[1024];  // [j][c]: (p0,p1,p2,-)
    __shared__ __align__(16) float sstage[8][256];
    int tid = threadIdx.x;
    for (int i = tid; i < 33 * 32; i += 256) sWr1[i] = Wr1[i];
    if (tid < 32) sbr1[tid] = br1[tid];
    for (int i = tid; i < 1024; i += 256) {
        int j = i >> 5, c = i & 31;
        const float* row = Wr2 + j * 224;
        sW2a[i] = make_float4(row[c], row[32 + c], row[64 + c], 0.f);
    }
    __syncthreads();
    int lane = tid & 31, warp = tid >> 5;
    int e0 = blockIdx.x * 64 + warp * 8;
    float* sst = sstage[warp];

    float t0, t1, t2, t3, t4, t5, t6, t7;
    t0 = edge_feat[(size_t)(e0 + 0) * 32 + lane];
    t1 = edge_feat[(size_t)(e0 + 1) * 32 + lane];
    t2 = edge_feat[(size_t)(e0 + 2) * 32 + lane];
    t3 = edge_feat[(size_t)(e0 + 3) * 32 + lane];
    t4 = edge_feat[(size_t)(e0 + 4) * 32 + lane];
    t5 = edge_feat[(size_t)(e0 + 5) * 32 + lane];
    t6 = edge_feat[(size_t)(e0 + 6) * 32 + lane];
    t7 = edge_feat[(size_t)(e0 + 7) * 32 + lane];
    {
        float4* sp = (float4*)(sst + lane * 8);
        sp[0] = make_float4(t0, t1, t2, t3);
        sp[1] = make_float4(t4, t5, t6, t7);
    }
    __syncwarp();

    float bia = sbr1[lane], w0l = sWr1[lane];
    t0 = fmaf(g_geom[(size_t)(e0 + 0) * 4], w0l, bia);
    t1 = fmaf(g_geom[(size_t)(e0 + 1) * 4], w0l, bia);
    t2 = fmaf(g_geom[(size_t)(e0 + 2) * 4], w0l, bia);
    t3 = fmaf(g_geom[(size_t)(e0 + 3) * 4], w0l, bia);
    t4 = fmaf(g_geom[(size_t)(e0 + 4) * 4], w0l, bia);
    t5 = fmaf(g_geom[(size_t)(e0 + 5) * 4], w0l, bia);
    t6 = fmaf(g_geom[(size_t)(e0 + 6) * 4], w0l, bia);
    t7 = fmaf(g_geom[(size_t)(e0 + 7) * 4], w0l, bia);
    ull h01, h23, h45, h67;
    PACK2(h01, t0, t1); PACK2(h23, t2, t3); PACK2(h45, t4, t5); PACK2(h67, t6, t7);
#pragma unroll
    for (int i = 0; i < 32; i++) {
        const ull* xp = (const ull*)(sst + i * 8);
        ull x01 = xp[0], x23 = xp[1], x45 = xp[2], x67 = xp[3];
        float wc = sWr1[(i + 1) * 32 + lane];
        ull wd; PACK2(wd, wc, wc);
        FMA2(h01, x01, wd); FMA2(h23, x23, wd); FMA2(h45, x45, wd); FMA2(h67, x67, wd);
    }
    UNPACK2(t0, t1, h01); UNPACK2(t2, t3, h23); UNPACK2(t4, t5, h45); UNPACK2(t6, t7, h67);
    t0 = fmaxf(t0, 0.f); t1 = fmaxf(t1, 0.f); t2 = fmaxf(t2, 0.f); t3 = fmaxf(t3, 0.f);
    t4 = fmaxf(t4, 0.f); t5 = fmaxf(t5, 0.f); t6 = fmaxf(t6, 0.f); t7 = fmaxf(t7, 0.f);
    __syncwarp();
    {
        float4* sp = (float4*)(sst + lane * 8);
        sp[0] = make_float4(t0, t1, t2, t3);
        sp[1] = make_float4(t4, t5, t6, t7);
    }
    __syncwarp();

    ull ac0[4] = {0, 0, 0, 0}, ac1[4] = {0, 0, 0, 0}, ac2[4] = {0, 0, 0, 0};
#pragma unroll
    for (int j = 0; j < 32; j++) {
        const ull* hp = (const ull*)(sst + j * 8);
        ull p01 = hp[0], p23 = hp[1], p45 = hp[2], p67 = hp[3];
        float4 a = sW2a[j * 32 + lane];
        ull wa, wb, wc2;
        PACK2(wa, a.x, a.x); PACK2(wb, a.y, a.y); PACK2(wc2, a.z, a.z);
        FMA2(ac0[0], p01, wa); FMA2(ac0[1], p23, wa); FMA2(ac0[2], p45, wa); FMA2(ac0[3], p67, wa);
        FMA2(ac1[0], p01, wb); FMA2(ac1[1], p23, wb); FMA2(ac1[2], p45, wb); FMA2(ac1[3], p67, wb);
        FMA2(ac2[0], p01, wc2); FMA2(ac2[1], p23, wc2); FMA2(ac2[2], p45, wc2); FMA2(ac2[3], p67, wc2);
    }

#pragma unroll
    for (int q2 = 0; q2 < 4; q2++) {
        float W0a, W0b, W1a, W1b, W2a, W2b;
        UNPACK2(W0a, W0b, ac0[q2]);
        UNPACK2(W1a, W1b, ac1[q2]);
        UNPACK2(W2a, W2b, ac2[q2]);
#pragma unroll
        for (int kk = 0; kk < 2; kk++) {
            int e = e0 + q2 * 2 + kk;
            float W0 = kk ? W0b : W0a, W1 = kk ? W1b : W1a, W2 = kk ? W2b : W2a;
            int src = esrc[e], dst = edst[e];
            float f0s = g_f0[(size_t)src * 32 + lane];
            float4 gm = ((const float4*)g_geom)[e];
            float ux = gm.y, uy = gm.z, uz = gm.w;
            const float* f1p = &g_f1[(size_t)src * 96 + lane * 3];
            const float* f2p = &g_f2[(size_t)src * 160 + lane * 5];
            float d1 = f1p[0] * ux + f1p[1] * uy + f1p[2] * uz;
            float s0 = ux * uy, s1 = uy * uz, s2 = 3.f * uz * uz - 1.f;
            float s3 = ux * uz, s4 = ux * ux - uy * uy;
            float d2 = f2p[0] * s0 + f2p[1] * s1 + f2p[2] * s2 + f2p[3] * s3 + f2p[4] * s4;
            float m0 = fmaf(W1, d1, fmaf(W2, d2, W0 * f0s));
            g_m0[(size_t)e * 32 + lane] = m0;
            const float* ktp = &g_kt[(size_t)dst * 128];
            float lg = 0.f;
#pragma unroll
            for (int h = 0; h < 4; h++) {
                float v = m0 * ktp[h * 32 + lane];
                v += __shfl_xor_sync(FULLMASK, v, 16);
                v += __shfl_xor_sync(FULLMASK, v, 8);
                v += __shfl_xor_sync(FULLMASK, v, 4);
                v += __shfl_xor_sync(FULLMASK, v, 2);
                v += __shfl_xor_sync(FULLMASK, v, 1);
                if (lane == h) lg = v;
            }
            if (lane < 4)
                g_logit[(size_t)e * 4 + lane] = lg * 0.35355339059327373f;
        }
    }
}

// ---------------- 9) layer-1 aggregation: softmax + a0 only (agg1/agg2 dead) ----------------
__global__ __launch_bounds__(256) void agg_l1_kernel() {
    int tid = threadIdx.x;
    int lane = tid & 31;
    int n = blockIdx.x * 8 + (tid >> 5);
    if (n >= Nn) return;
    int beg = g_off[n], end = g_off[n + 1];
    int grp = lane >> 3;

    float mx = -3.0e38f;
    for (int i = beg; i < end; i++)
        mx = fmaxf(mx, g_logit[(size_t)g_eid[i] * 4 + grp]);

    float den = 0.f, a0 = 0.f;
#pragma unroll 2
    for (int i = beg; i < end; i++) {
        int eid = g_eid[i];
        float ee = __expf(g_logit[(size_t)eid * 4 + grp] - mx);
        den += ee;
        a0 = fmaf(ee, g_m0[(size_t)eid * 32 + lane], a0);
    }
    g_agg0[(size_t)n * 32 + lane] = a0 / (den + 1e-8f);
}

// ---------------- 10) layer-1 f0 update + output ----------------
__global__ __launch_bounds__(256) void update_out_kernel(
    const float* __restrict__ Ws0, const float* __restrict__ Wsk,
    const float* __restrict__ Wout, const float* __restrict__ Wc,
    float* __restrict__ out) {
    __shared__ __align__(16) float s0[1024], sk[1024], sWo[1024];
    __shared__ float sWc[480];
    int tid = threadIdx.x;
    for (int i = tid; i < 1024; i += 256) {
        s0[i] = Ws0[i]; sk[i] = Wsk[i]; sWo[i] = Wout[i];
    }
    for (int i = tid; i < 480; i += 256) sWc[i] = Wc[i];
    __syncthreads();
    int warp = tid >> 5, lane = tid & 31;
    int n = blockIdx.x * 8 + warp;
    if (n >= Nn) return;
    float f = g_f0[(size_t)n * 32 + lane];
    float a = g_agg0[(size_t)n * 32 + lane];
    float o0 = 0.f;
#pragma unroll
    for (int c = 0; c < 32; c++) {
        float fc = __shfl_sync(FULLMASK, f, c);
        float ac = __shfl_sync(FULLMASK, a, c);
        o0 += ac * s0[c * 32 + lane] + fc * sk[c * 32 + lane];
    }
    float hs = 0.f;
#pragma unroll
    for (int c = 0; c < 32; c++) {
        float oc = __shfl_sync(FULLMASK, o0, c);
        hs = fmaf(oc, sWo[c * 32 + lane], hs);
    }
    out[(size_t)n * 32 + lane] = hs;
    float cacc = 0.f;
#pragma unroll
    for (int j = 0; j < 32; j++) {
        float hj = __shfl_sync(FULLMASK, hs, j);
        if (lane < 15) cacc = fmaf(hj, sWc[j * 15 + lane], cacc);
    }
    if (lane < 15) out[(size_t)Nn * 32 + (size_t)n * 15 + lane] = cacc;
}

// ---------------- launch ----------------
extern "C" void kernel_launch(void* const* d_in, const int* in_sizes, int n_in,
                              void* d_out, int out_size) {
    const float* pos       = (const float*)d_in[0];
    const float* node_l0   = (const float*)d_in[1];
    const float* edge_feat = (const float*)d_in[2];
    const int*   esrc      = (const int*)d_in[3];
    const int*   edst      = (const int*)d_in[4];
    const float* Wr1       = (const float*)d_in[5];
    const float* br1       = (const float*)d_in[6];
    const float* Wr2       = (const float*)d_in[7];
    const float* Wq        = (const float*)d_in[8];
    const float* Wk        = (const float*)d_in[9];
    const float* Ws0       = (const float*)d_in[10];
    const float* Ws1       = (const float*)d_in[11];
    const float* Ws2       = (const float*)d_in[12];
    const float* Wsk       = (const float*)d_in[13];
    const float* Wout      = (const float*)d_in[14];
    const float* Wc        = (const float*)d_in[15];
    float* out = (float*)d_out;

    const int NODE_BLKS = (Nn + 7) / 8;    // warp-per-node: 8 nodes / block
    const int EDGE_BLKS = Ee / 64;         // warp-per-8-edges: 64 edges / block

    init_kt_kernel<<<NODE_BLKS, 256>>>(node_l0, Wq, Wk);                     // 1
    geom_hist_kernel<<<(Ee + 255) / 256, 256>>>(pos, esrc, edst);            // 2
    scan_kernel<<<1, 1024>>>();                                              // 3
    edge_l0_kernel<<<EDGE_BLKS, 256>>>(edge_feat, esrc, edst, Wr1, br1, Wr2);// 4 (profiled slot)
    scatter_kernel<<<(Ee + 255) / 256, 256>>>(edst);                         // 5
    agg_l0_kernel<<<NODE_BLKS, 256>>>(esrc);                                 // 6
    update_l0_kt_kernel<<<NODE_BLKS, 256>>>(Ws0, Ws1, Ws2, Wsk,
                                            Wq + 1024, Wk + 1024);           // 7
    edge_l1_kernel<<<EDGE_BLKS, 256>>>(edge_feat, esrc, edst, Wr1 + 1056,
                                       br1 + 32, Wr2 + 7168);                // 8
    agg_l1_kernel<<<NODE_BLKS, 256>>>();                                     // 9
    update_out_kernel<<<NODE_BLKS, 256>>>(Ws0 + 1024, Wsk + 1024, Wout, Wc, out); // 10
}

// round 6
// speedup vs baseline: 4.2025x; 1.0500x over previous
#include <cuda_runtime.h>

#define Nn 30000
#define Ee 480000
#define FULLMASK 0xffffffffu

typedef unsigned long long ull;

// packed fp32x2 helpers (Blackwell FFMA2 path — PTX only)
#define PACK2(d, lo, hi) asm("mov.b64 %0, {%1, %2};" : "=l"(d) : "f"(lo), "f"(hi))
#define UNPACK2(lo, hi, s) asm("mov.b64 {%0, %1}, %2;" : "=f"(lo), "=f"(hi) : "l"(s))
#define FMA2(acc, a, b) asm("fma.rn.f32x2 %0, %1, %2, %0;" : "+l"(acc) : "l"(a), "l"(b))

// ---------------- scratch (static device allocations; no cudaMalloc) ----------------
__device__ __align__(16) float g_geom[Ee * 4];   // r, ux, uy, uz
__device__ __align__(16) float g_m0[Ee * 32];
__device__ __align__(16) float g_w[Ee * 64];     // layer0: [E][32] float2 (w3,w5)
__device__ __align__(16) float g_logit[Ee * 4];
__device__ __align__(16) float g_kt[Nn * 128];   // permuted: [(c>>3)*32 + h*8 + (c&7)]
__device__ float g_f0[Nn * 32];
__device__ float g_f1[Nn * 96];    // planar [n][3][32]
__device__ float g_f2[Nn * 160];   // planar [n][5][32]
__device__ float g_agg[Nn * 288];  // planar [n][9][32]
__device__ float g_agg0[Nn * 32];  // layer1: [n][c]
__device__ int g_deg[Nn];
__device__ int g_off[Nn + 1];
__device__ int g_cur[Nn];
__device__ int g_eid[Ee];

// kt permutation: value for (head h, channel c) stored at (c>>3)*32 + h*8 + (c&7)
__device__ __forceinline__ int kt_perm(int h, int c) {
    return ((c >> 3) << 5) + (h << 3) + (c & 7);
}

// ---------------- 1) init: copy f0, zero deg, kt for layer 0 (warp per node) ----------------
__global__ __launch_bounds__(256) void init_kt_kernel(const float* __restrict__ node_l0,
                                                      const float* __restrict__ Wq,
                                                      const float* __restrict__ Wk) {
    __shared__ float sWq[1024];    // [c][j]
    __shared__ float sWkT[1024];   // [j][c]
    int tid = threadIdx.x;
    for (int i = tid; i < 1024; i += 256) {
        sWq[i] = Wq[i];
        int c = i >> 5, j = i & 31;
        sWkT[j * 32 + c] = Wk[i];
    }
    __syncthreads();
    int warp = tid >> 5, lane = tid & 31;
    int n = blockIdx.x * 8 + warp;
    if (n >= Nn) return;
    float f = node_l0[(size_t)n * 32 + lane];
    g_f0[(size_t)n * 32 + lane] = f;
    if (lane == 0) g_deg[n] = 0;
    float q = 0.f;
#pragma unroll
    for (int c = 0; c < 32; c++) {
        float fc = __shfl_sync(FULLMASK, f, c);
        q = fmaf(fc, sWq[c * 32 + lane], q);
    }
#pragma unroll
    for (int h = 0; h < 4; h++) {
        float kt = 0.f;
#pragma unroll
        for (int d = 0; d < 8; d++) {
            float qd = __shfl_sync(FULLMASK, q, h * 8 + d);
            kt = fmaf(qd, sWkT[(h * 8 + d) * 32 + lane], kt);
        }
        g_kt[(size_t)n * 128 + kt_perm(h, lane)] = kt;
    }
}

// ---------------- 2) geometry + degree histogram ----------------
__global__ void geom_hist_kernel(const float* __restrict__ pos,
                                 const int* __restrict__ esrc,
                                 const int* __restrict__ edst) {
    int e = blockIdx.x * blockDim.x + threadIdx.x;
    if (e >= Ee) return;
    int s = esrc[e], d = edst[e];
    float rx = pos[d * 3 + 0] - pos[s * 3 + 0];
    float ry = pos[d * 3 + 1] - pos[s * 3 + 1];
    float rz = pos[d * 3 + 2] - pos[s * 3 + 2];
    float r = sqrtf(rx * rx + ry * ry + rz * rz + 1e-8f);
    float inv = 1.0f / r;
    ((float4*)g_geom)[e] = make_float4(r, rx * inv, ry * inv, rz * inv);
    atomicAdd(&g_deg[d], 1);
}

// ---------------- 3) exclusive scan (writes g_off and g_cur) ----------------
__global__ void scan_kernel() {
    __shared__ int sp[1024];
    const int CH = 30;
    int t = threadIdx.x;
    int loc[CH];
    int base = t * CH;
    int s = 0;
#pragma unroll
    for (int i = 0; i < CH; i++) {
        int idx = base + i;
        int v = (idx < Nn) ? g_deg[idx] : 0;
        loc[i] = v;
        s += v;
    }
    sp[t] = s;
    __syncthreads();
    for (int off = 1; off < 1024; off <<= 1) {
        int v = (t >= off) ? sp[t - off] : 0;
        __syncthreads();
        sp[t] += v;
        __syncthreads();
    }
    int run = (t == 0) ? 0 : sp[t - 1];
#pragma unroll
    for (int i = 0; i < CH; i++) {
        int idx = base + i;
        if (idx < Nn) { g_off[idx] = run; g_cur[idx] = run; run += loc[i]; }
    }
    if (t == 1023) g_off[Nn] = sp[1023];
}

// ---------------- 5) scatter edge ids by dst ----------------
__global__ void scatter_kernel(const int* __restrict__ edst) {
    int e = blockIdx.x * blockDim.x + threadIdx.x;
    if (e >= Ee) return;
    int d = edst[e];
    int p = atomicAdd(&g_cur[d], 1);
    g_eid[p] = e;
}

// ---------------- 4) layer-0 edge kernel (warp per 8 edges; f1=f2=0) ----------------
__global__ __launch_bounds__(256) void edge_l0_kernel(
    const float* __restrict__ edge_feat, const int* __restrict__ esrc,
    const int* __restrict__ edst, const float* __restrict__ Wr1,
    const float* __restrict__ br1, const float* __restrict__ Wr2) {
    __shared__ __align__(16) float sWr1[33 * 32];
    __shared__ float sbr1[32];
    __shared__ __align__(16) float4 sW2a[1024];  // [j][c]: (p0,p3,p5,-)
    __shared__ __align__(16) float sstage[8][256];
    int tid = threadIdx.x;
    for (int i = tid; i < 33 * 32; i += 256) sWr1[i] = Wr1[i];
    if (tid < 32) sbr1[tid] = br1[tid];
    for (int i = tid; i < 1024; i += 256) {
        int j = i >> 5, c = i & 31;
        const float* row = Wr2 + j * 224;
        sW2a[i] = make_float4(row[c], row[96 + c], row[160 + c], 0.f);
    }
    __syncthreads();
    int lane = tid & 31, warp = tid >> 5;
    int e0 = blockIdx.x * 64 + warp * 8;
    float* sst = sstage[warp];

    float t0, t1, t2, t3, t4, t5, t6, t7;
    t0 = edge_feat[(size_t)(e0 + 0) * 32 + lane];
    t1 = edge_feat[(size_t)(e0 + 1) * 32 + lane];
    t2 = edge_feat[(size_t)(e0 + 2) * 32 + lane];
    t3 = edge_feat[(size_t)(e0 + 3) * 32 + lane];
    t4 = edge_feat[(size_t)(e0 + 4) * 32 + lane];
    t5 = edge_feat[(size_t)(e0 + 5) * 32 + lane];
    t6 = edge_feat[(size_t)(e0 + 6) * 32 + lane];
    t7 = edge_feat[(size_t)(e0 + 7) * 32 + lane];
    {
        float4* sp = (float4*)(sst + lane * 8);
        sp[0] = make_float4(t0, t1, t2, t3);
        sp[1] = make_float4(t4, t5, t6, t7);
    }
    __syncwarp();

    float bia = sbr1[lane], w0l = sWr1[lane];
    t0 = fmaf(g_geom[(size_t)(e0 + 0) * 4], w0l, bia);
    t1 = fmaf(g_geom[(size_t)(e0 + 1) * 4], w0l, bia);
    t2 = fmaf(g_geom[(size_t)(e0 + 2) * 4], w0l, bia);
    t3 = fmaf(g_geom[(size_t)(e0 + 3) * 4], w0l, bia);
    t4 = fmaf(g_geom[(size_t)(e0 + 4) * 4], w0l, bia);
    t5 = fmaf(g_geom[(size_t)(e0 + 5) * 4], w0l, bia);
    t6 = fmaf(g_geom[(size_t)(e0 + 6) * 4], w0l, bia);
    t7 = fmaf(g_geom[(size_t)(e0 + 7) * 4], w0l, bia);
    ull h01, h23, h45, h67;
    PACK2(h01, t0, t1); PACK2(h23, t2, t3); PACK2(h45, t4, t5); PACK2(h67, t6, t7);
#pragma unroll
    for (int i = 0; i < 32; i++) {
        const ulonglong2* xp = (const ulonglong2*)(sst + i * 8);
        ulonglong2 xa = xp[0], xb = xp[1];   // LDS.128 x2
        float wc = sWr1[(i + 1) * 32 + lane];
        ull wd; PACK2(wd, wc, wc);
        FMA2(h01, xa.x, wd); FMA2(h23, xa.y, wd); FMA2(h45, xb.x, wd); FMA2(h67, xb.y, wd);
    }
    UNPACK2(t0, t1, h01); UNPACK2(t2, t3, h23); UNPACK2(t4, t5, h45); UNPACK2(t6, t7, h67);
    t0 = fmaxf(t0, 0.f); t1 = fmaxf(t1, 0.f); t2 = fmaxf(t2, 0.f); t3 = fmaxf(t3, 0.f);
    t4 = fmaxf(t4, 0.f); t5 = fmaxf(t5, 0.f); t6 = fmaxf(t6, 0.f); t7 = fmaxf(t7, 0.f);
    __syncwarp();
    {
        float4* sp = (float4*)(sst + lane * 8);
        sp[0] = make_float4(t0, t1, t2, t3);
        sp[1] = make_float4(t4, t5, t6, t7);
    }
    __syncwarp();

    ull ac0[4] = {0, 0, 0, 0}, ac3[4] = {0, 0, 0, 0}, ac5[4] = {0, 0, 0, 0};
#pragma unroll
    for (int j = 0; j < 32; j++) {
        const ulonglong2* hp = (const ulonglong2*)(sst + j * 8);
        ulonglong2 ha = hp[0], hb = hp[1];   // LDS.128 x2
        float4 a = sW2a[j * 32 + lane];
        ull wa, wb, wc2;
        PACK2(wa, a.x, a.x); PACK2(wb, a.y, a.y); PACK2(wc2, a.z, a.z);
        FMA2(ac0[0], ha.x, wa); FMA2(ac0[1], ha.y, wa); FMA2(ac0[2], hb.x, wa); FMA2(ac0[3], hb.y, wa);
        FMA2(ac3[0], ha.x, wb); FMA2(ac3[1], ha.y, wb); FMA2(ac3[2], hb.x, wb); FMA2(ac3[3], hb.y, wb);
        FMA2(ac5[0], ha.x, wc2); FMA2(ac5[1], ha.y, wc2); FMA2(ac5[2], hb.x, wc2); FMA2(ac5[3], hb.y, wc2);
    }

    int sub = lane & 7;
#pragma unroll
    for (int q2 = 0; q2 < 4; q2++) {
        float W0a, W0b, W3a, W3b, W5a, W5b;
        UNPACK2(W0a, W0b, ac0[q2]);
        UNPACK2(W3a, W3b, ac3[q2]);
        UNPACK2(W5a, W5b, ac5[q2]);
#pragma unroll
        for (int kk = 0; kk < 2; kk++) {
            int e = e0 + q2 * 2 + kk;
            float W0 = kk ? W0b : W0a, W3 = kk ? W3b : W3a, W5 = kk ? W5b : W5a;
            int src = esrc[e], dst = edst[e];
            float f0s = g_f0[(size_t)src * 32 + lane];
            float m0 = W0 * f0s;
            g_m0[(size_t)e * 32 + lane] = m0;
            ((float2*)g_w)[(size_t)e * 32 + lane] = make_float2(W3, W5);
            // logit: lane -> (head = lane>>3, partial over ch sub+8k)
            const float* ktp = &g_kt[(size_t)dst * 128];
            float v = 0.f;
#pragma unroll
            for (int k2 = 0; k2 < 4; k2++) {
                float mc = __shfl_sync(FULLMASK, m0, sub + 8 * k2);
                v = fmaf(mc, ktp[k2 * 32 + lane], v);
            }
            v += __shfl_xor_sync(FULLMASK, v, 1);
            v += __shfl_xor_sync(FULLMASK, v, 2);
            v += __shfl_xor_sync(FULLMASK, v, 4);
            if (sub == 0)
                g_logit[(size_t)e * 4 + (lane >> 3)] = v * 0.35355339059327373f;
        }
    }
}

// ---------------- 6) layer-0 aggregation (warp per node) ----------------
__global__ __launch_bounds__(256) void agg_l0_kernel(const int* __restrict__ esrc) {
    int tid = threadIdx.x;
    int lane = tid & 31;
    int n = blockIdx.x * 8 + (tid >> 5);
    if (n >= Nn) return;
    int beg = g_off[n], end = g_off[n + 1];
    int grp = lane >> 3;

    float mx = -3.0e38f;
    for (int i = beg; i < end; i++)
        mx = fmaxf(mx, g_logit[(size_t)g_eid[i] * 4 + grp]);

    float den = 0.f;
    float a0 = 0.f, a10 = 0.f, a11 = 0.f, a12 = 0.f;
    float a20 = 0.f, a21 = 0.f, a22 = 0.f, a23 = 0.f, a24 = 0.f;
#pragma unroll 2
    for (int i = beg; i < end; i++) {
        int eid = g_eid[i];
        float ee = __expf(g_logit[(size_t)eid * 4 + grp] - mx);
        den += ee;
        float m0 = g_m0[(size_t)eid * 32 + lane];
        float4 gm = ((const float4*)g_geom)[eid];
        float ux = gm.y, uy = gm.z, uz = gm.w;
        int src = esrc[eid];
        float f0s = g_f0[(size_t)src * 32 + lane];
        a0 = fmaf(ee, m0, a0);
        float y0 = ux * uy, y1 = uy * uz, y2 = 3.f * uz * uz - 1.f;
        float y3 = ux * uz, y4 = ux * ux - uy * uy;
        float2 w = ((const float2*)g_w)[(size_t)eid * 32 + lane];
        float wf3 = w.x * f0s * ee, wf5 = w.y * f0s * ee;
        a10 = fmaf(wf3, ux, a10); a11 = fmaf(wf3, uy, a11); a12 = fmaf(wf3, uz, a12);
        a20 = fmaf(wf5, y0, a20); a21 = fmaf(wf5, y1, a21); a22 = fmaf(wf5, y2, a22);
        a23 = fmaf(wf5, y3, a23); a24 = fmaf(wf5, y4, a24);
    }
    float dinv = 1.f / (den + 1e-8f);
    float* ag = &g_agg[(size_t)n * 288];   // planar [9][32]
    ag[0 * 32 + lane] = a0 * dinv;
    ag[1 * 32 + lane] = a10 * dinv; ag[2 * 32 + lane] = a11 * dinv; ag[3 * 32 + lane] = a12 * dinv;
    ag[4 * 32 + lane] = a20 * dinv; ag[5 * 32 + lane] = a21 * dinv; ag[6 * 32 + lane] = a22 * dinv;
    ag[7 * 32 + lane] = a23 * dinv; ag[8 * 32 + lane] = a24 * dinv;
}

// ---------------- 7) layer-0 update (writes f0,f1,f2 planar) + kt for layer 1 ----------------
__global__ __launch_bounds__(256) void update_l0_kt_kernel(
    const float* __restrict__ Ws0, const float* __restrict__ Ws1,
    const float* __restrict__ Ws2, const float* __restrict__ Wsk,
    const float* __restrict__ Wq, const float* __restrict__ Wk) {
    __shared__ __align__(16) float s0[1024], s1[1024], s2[1024], sk[1024];
    __shared__ float sWq[1024], sWkT[1024];
    __shared__ __align__(16) float sag[8][384];   // [c][12] padded
    int tid = threadIdx.x;
    for (int i = tid; i < 1024; i += 256) {
        s0[i] = Ws0[i]; s1[i] = Ws1[i]; s2[i] = Ws2[i]; sk[i] = Wsk[i];
        sWq[i] = Wq[i];
        int c = i >> 5, j = i & 31;
        sWkT[j * 32 + c] = Wk[i];
    }
    __syncthreads();
    int warp = tid >> 5, lane = tid & 31;
    int n = blockIdx.x * 8 + warp;
    if (n >= Nn) return;
    float f = g_f0[(size_t)n * 32 + lane];
    {
        const float* ag = &g_agg[(size_t)n * 288];
#pragma unroll
        for (int s = 0; s < 9; s++)
            sag[warp][lane * 12 + s] = ag[s * 32 + lane];
    }
    __syncwarp();
    float o0 = 0.f, o10 = 0.f, o11 = 0.f, o12 = 0.f;
    float o20 = 0.f, o21 = 0.f, o22 = 0.f, o23 = 0.f, o24 = 0.f;
#pragma unroll 4
    for (int c = 0; c < 32; c++) {
        const float* ac = &sag[warp][c * 12];
        float4 A0 = *(const float4*)ac;        // agg0, a10, a11, a12
        float4 A1 = *(const float4*)(ac + 4);  // a20..a23
        float A8 = ac[8];                      // a24
        float fc = __shfl_sync(FULLMASK, f, c);
        o0 += A0.x * s0[c * 32 + lane] + fc * sk[c * 32 + lane];
        float w1 = s1[c * 32 + lane];
        o10 += A0.y * w1; o11 += A0.z * w1; o12 += A0.w * w1;
        float w2 = s2[c * 32 + lane];
        o20 += A1.x * w2; o21 += A1.y * w2; o22 += A1.z * w2;
        o23 += A1.w * w2; o24 += A8 * w2;
    }
    g_f0[(size_t)n * 32 + lane] = o0;
    float* f1w = &g_f1[(size_t)n * 96];   // planar [3][32]
    f1w[0 * 32 + lane] = o10; f1w[1 * 32 + lane] = o11; f1w[2 * 32 + lane] = o12;
    float* f2w = &g_f2[(size_t)n * 160];  // planar [5][32]
    f2w[0 * 32 + lane] = o20; f2w[1 * 32 + lane] = o21; f2w[2 * 32 + lane] = o22;
    f2w[3 * 32 + lane] = o23; f2w[4 * 32 + lane] = o24;
    // kt for layer 1 from updated f0
    float q = 0.f;
#pragma unroll
    for (int c = 0; c < 32; c++) {
        float fc = __shfl_sync(FULLMASK, o0, c);
        q = fmaf(fc, sWq[c * 32 + lane], q);
    }
#pragma unroll
    for (int h = 0; h < 4; h++) {
        float kt = 0.f;
#pragma unroll
        for (int d = 0; d < 8; d++) {
            float qd = __shfl_sync(FULLMASK, q, h * 8 + d);
            kt = fmaf(qd, sWkT[(h * 8 + d) * 32 + lane], kt);
        }
        g_kt[(size_t)n * 128 + kt_perm(h, lane)] = kt;
    }
}

// ---------------- 8) layer-1 edge kernel (only w0,w1,w2 — agg1/agg2 are dead) ----------------
__global__ __launch_bounds__(256) void edge_l1_kernel(
    const float* __restrict__ edge_feat, const int* __restrict__ esrc,
    const int* __restrict__ edst, const float* __restrict__ Wr1,
    const float* __restrict__ br1, const float* __restrict__ Wr2) {
    __shared__ __align__(16) float sWr1[33 * 32];
    __shared__ float sbr1[32];
    __shared__ __align__(16) float4 sW2a[1024];  // [j][c]: (p0,p1,p2,-)
    __shared__ __align__(16) float sstage[8][256];
    int tid = threadIdx.x;
    for (int i = tid; i < 33 * 32; i += 256) sWr1[i] = Wr1[i];
    if (tid < 32) sbr1[tid] = br1[tid];
    for (int i = tid; i < 1024; i += 256) {
        int j = i >> 5, c = i & 31;
        const float* row = Wr2 + j * 224;
        sW2a[i] = make_float4(row[c], row[32 + c], row[64 + c], 0.f);
    }
    __syncthreads();
    int lane = tid & 31, warp = tid >> 5;
    int e0 = blockIdx.x * 64 + warp * 8;
    float* sst = sstage[warp];

    float t0, t1, t2, t3, t4, t5, t6, t7;
    t0 = edge_feat[(size_t)(e0 + 0) * 32 + lane];
    t1 = edge_feat[(size_t)(e0 + 1) * 32 + lane];
    t2 = edge_feat[(size_t)(e0 + 2) * 32 + lane];
    t3 = edge_feat[(size_t)(e0 + 3) * 32 + lane];
    t4 = edge_feat[(size_t)(e0 + 4) * 32 + lane];
    t5 = edge_feat[(size_t)(e0 + 5) * 32 + lane];
    t6 = edge_feat[(size_t)(e0 + 6) * 32 + lane];
    t7 = edge_feat[(size_t)(e0 + 7) * 32 + lane];
    {
        float4* sp = (float4*)(sst + lane * 8);
        sp[0] = make_float4(t0, t1, t2, t3);
        sp[1] = make_float4(t4, t5, t6, t7);
    }
    __syncwarp();

    float bia = sbr1[lane], w0l = sWr1[lane];
    t0 = fmaf(g_geom[(size_t)(e0 + 0) * 4], w0l, bia);
    t1 = fmaf(g_geom[(size_t)(e0 + 1) * 4], w0l, bia);
    t2 = fmaf(g_geom[(size_t)(e0 + 2) * 4], w0l, bia);
    t3 = fmaf(g_geom[(size_t)(e0 + 3) * 4], w0l, bia);
    t4 = fmaf(g_geom[(size_t)(e0 + 4) * 4], w0l, bia);
    t5 = fmaf(g_geom[(size_t)(e0 + 5) * 4], w0l, bia);
    t6 = fmaf(g_geom[(size_t)(e0 + 6) * 4], w0l, bia);
    t7 = fmaf(g_geom[(size_t)(e0 + 7) * 4], w0l, bia);
    ull h01, h23, h45, h67;
    PACK2(h01, t0, t1); PACK2(h23, t2, t3); PACK2(h45, t4, t5); PACK2(h67, t6, t7);
#pragma unroll
    for (int i = 0; i < 32; i++) {
        const ulonglong2* xp = (const ulonglong2*)(sst + i * 8);
        ulonglong2 xa = xp[0], xb = xp[1];
        float wc = sWr1[(i + 1) * 32 + lane];
        ull wd; PACK2(wd, wc, wc);
        FMA2(h01, xa.x, wd); FMA2(h23, xa.y, wd); FMA2(h45, xb.x, wd); FMA2(h67, xb.y, wd);
    }
    UNPACK2(t0, t1, h01); UNPACK2(t2, t3, h23); UNPACK2(t4, t5, h45); UNPACK2(t6, t7, h67);
    t0 = fmaxf(t0, 0.f); t1 = fmaxf(t1, 0.f); t2 = fmaxf(t2, 0.f); t3 = fmaxf(t3, 0.f);
    t4 = fmaxf(t4, 0.f); t5 = fmaxf(t5, 0.f); t6 = fmaxf(t6, 0.f); t7 = fmaxf(t7, 0.f);
    __syncwarp();
    {
        float4* sp = (float4*)(sst + lane * 8);
        sp[0] = make_float4(t0, t1, t2, t3);
        sp[1] = make_float4(t4, t5, t6, t7);
    }
    __syncwarp();

    ull ac0[4] = {0, 0, 0, 0}, ac1[4] = {0, 0, 0, 0}, ac2[4] = {0, 0, 0, 0};
#pragma unroll
    for (int j = 0; j < 32; j++) {
        const ulonglong2* hp = (const ulonglong2*)(sst + j * 8);
        ulonglong2 ha = hp[0], hb = hp[1];
        float4 a = sW2a[j * 32 + lane];
        ull wa, wb, wc2;
        PACK2(wa, a.x, a.x); PACK2(wb, a.y, a.y); PACK2(wc2, a.z, a.z);
        FMA2(ac0[0], ha.x, wa); FMA2(ac0[1], ha.y, wa); FMA2(ac0[2], hb.x, wa); FMA2(ac0[3], hb.y, wa);
        FMA2(ac1[0], ha.x, wb); FMA2(ac1[1], ha.y, wb); FMA2(ac1[2], hb.x, wb); FMA2(ac1[3], hb.y, wb);
        FMA2(ac2[0], ha.x, wc2); FMA2(ac2[1], ha.y, wc2); FMA2(ac2[2], hb.x, wc2); FMA2(ac2[3], hb.y, wc2);
    }

    int sub = lane & 7;
#pragma unroll
    for (int q2 = 0; q2 < 4; q2++) {
        float W0a, W0b, W1a, W1b, W2a, W2b;
        UNPACK2(W0a, W0b, ac0[q2]);
        UNPACK2(W1a, W1b, ac1[q2]);
        UNPACK2(W2a, W2b, ac2[q2]);
#pragma unroll
        for (int kk = 0; kk < 2; kk++) {
            int e = e0 + q2 * 2 + kk;
            float W0 = kk ? W0b : W0a, W1 = kk ? W1b : W1a, W2 = kk ? W2b : W2a;
            int src = esrc[e], dst = edst[e];
            float f0s = g_f0[(size_t)src * 32 + lane];
            float4 gm = ((const float4*)g_geom)[e];
            float ux = gm.y, uy = gm.z, uz = gm.w;
            const float* f1p = &g_f1[(size_t)src * 96];    // planar [3][32]
            const float* f2p = &g_f2[(size_t)src * 160];   // planar [5][32]
            float d1 = f1p[lane] * ux + f1p[32 + lane] * uy + f1p[64 + lane] * uz;
            float s0 = ux * uy, s1 = uy * uz, s2 = 3.f * uz * uz - 1.f;
            float s3 = ux * uz, s4 = ux * ux - uy * uy;
            float d2 = f2p[lane] * s0 + f2p[32 + lane] * s1 + f2p[64 + lane] * s2 +
                       f2p[96 + lane] * s3 + f2p[128 + lane] * s4;
            float m0 = fmaf(W1, d1, fmaf(W2, d2, W0 * f0s));
            g_m0[(size_t)e * 32 + lane] = m0;
            const float* ktp = &g_kt[(size_t)dst * 128];
            float v = 0.f;
#pragma unroll
            for (int k2 = 0; k2 < 4; k2++) {
                float mc = __shfl_sync(FULLMASK, m0, sub + 8 * k2);
                v = fmaf(mc, ktp[k2 * 32 + lane], v);
            }
            v += __shfl_xor_sync(FULLMASK, v, 1);
            v += __shfl_xor_sync(FULLMASK, v, 2);
            v += __shfl_xor_sync(FULLMASK, v, 4);
            if (sub == 0)
                g_logit[(size_t)e * 4 + (lane >> 3)] = v * 0.35355339059327373f;
        }
    }
}

// ---------------- 9) layer-1 aggregation: softmax + a0 only ----------------
__global__ __launch_bounds__(256) void agg_l1_kernel() {
    int tid = threadIdx.x;
    int lane = tid & 31;
    int n = blockIdx.x * 8 + (tid >> 5);
    if (n >= Nn) return;
    int beg = g_off[n], end = g_off[n + 1];
    int grp = lane >> 3;

    float mx = -3.0e38f;
    for (int i = beg; i < end; i++)
        mx = fmaxf(mx, g_logit[(size_t)g_eid[i] * 4 + grp]);

    float den = 0.f, a0 = 0.f;
#pragma unroll 2
    for (int i = beg; i < end; i++) {
        int eid = g_eid[i];
        float ee = __expf(g_logit[(size_t)eid * 4 + grp] - mx);
        den += ee;
        a0 = fmaf(ee, g_m0[(size_t)eid * 32 + lane], a0);
    }
    g_agg0[(size_t)n * 32 + lane] = a0 / (den + 1e-8f);
}

// ---------------- 10) layer-1 f0 update + output ----------------
__global__ __launch_bounds__(256) void update_out_kernel(
    const float* __restrict__ Ws0, const float* __restrict__ Wsk,
    const float* __restrict__ Wout, const float* __restrict__ Wc,
    float* __restrict__ out) {
    __shared__ __align__(16) float s0[1024], sk[1024], sWo[1024];
    __shared__ float sWc[480];
    int tid = threadIdx.x;
    for (int i = tid; i < 1024; i += 256) {
        s0[i] = Ws0[i]; sk[i] = Wsk[i]; sWo[i] = Wout[i];
    }
    for (int i = tid; i < 480; i += 256) sWc[i] = Wc[i];
    __syncthreads();
    int warp = tid >> 5, lane = tid & 31;
    int n = blockIdx.x * 8 + warp;
    if (n >= Nn) return;
    float f = g_f0[(size_t)n * 32 + lane];
    float a = g_agg0[(size_t)n * 32 + lane];
    float o0 = 0.f;
#pragma unroll
    for (int c = 0; c < 32; c++) {
        float fc = __shfl_sync(FULLMASK, f, c);
        float ac = __shfl_sync(FULLMASK, a, c);
        o0 += ac * s0[c * 32 + lane] + fc * sk[c * 32 + lane];
    }
    float hs = 0.f;
#pragma unroll
    for (int c = 0; c < 32; c++) {
        float oc = __shfl_sync(FULLMASK, o0, c);
        hs = fmaf(oc, sWo[c * 32 + lane], hs);
    }
    out[(size_t)n * 32 + lane] = hs;
    float cacc = 0.f;
#pragma unroll
    for (int j = 0; j < 32; j++) {
        float hj = __shfl_sync(FULLMASK, hs, j);
        if (lane < 15) cacc = fmaf(hj, sWc[j * 15 + lane], cacc);
    }
    if (lane < 15) out[(size_t)Nn * 32 + (size_t)n * 15 + lane] = cacc;
}

// ---------------- launch ----------------
extern "C" void kernel_launch(void* const* d_in, const int* in_sizes, int n_in,
                              void* d_out, int out_size) {
    const float* pos       = (const float*)d_in[0];
    const float* node_l0   = (const float*)d_in[1];
    const float* edge_feat = (const float*)d_in[2];
    const int*   esrc      = (const int*)d_in[3];
    const int*   edst      = (const int*)d_in[4];
    const float* Wr1       = (const float*)d_in[5];
    const float* br1       = (const float*)d_in[6];
    const float* Wr2       = (const float*)d_in[7];
    const float* Wq        = (const float*)d_in[8];
    const float* Wk        = (const float*)d_in[9];
    const float* Ws0       = (const float*)d_in[10];
    const float* Ws1       = (const float*)d_in[11];
    const float* Ws2       = (const float*)d_in[12];
    const float* Wsk       = (const float*)d_in[13];
    const float* Wout      = (const float*)d_in[14];
    const float* Wc        = (const float*)d_in[15];
    float* out = (float*)d_out;

    const int NODE_BLKS = (Nn + 7) / 8;
    const int EDGE_BLKS = Ee / 64;

    init_kt_kernel<<<NODE_BLKS, 256>>>(node_l0, Wq, Wk);                      // 1
    geom_hist_kernel<<<(Ee + 255) / 256, 256>>>(pos, esrc, edst);             // 2
    scan_kernel<<<1, 1024>>>();                                               // 3
    edge_l0_kernel<<<EDGE_BLKS, 256>>>(edge_feat, esrc, edst, Wr1, br1, Wr2); // 4 (profiled)
    scatter_kernel<<<(Ee + 255) / 256, 256>>>(edst);                          // 5
    agg_l0_kernel<<<NODE_BLKS, 256>>>(esrc);                                  // 6
    update_l0_kt_kernel<<<NODE_BLKS, 256>>>(Ws0, Ws1, Ws2, Wsk,
                                            Wq + 1024, Wk + 1024);            // 7
    edge_l1_kernel<<<EDGE_BLKS, 256>>>(edge_feat, esrc, edst, Wr1 + 1056,
                                       br1 + 32, Wr2 + 7168);                 // 8
    agg_l1_kernel<<<NODE_BLKS, 256>>>();                                      // 9
    update_out_kernel<<<NODE_BLKS, 256>>>(Ws0 + 1024, Wsk + 1024, Wout, Wc, out); // 10
}